// round 3
// baseline (speedup 1.0000x reference)
#include <cuda_runtime.h>
#include <cstdint>

#define N_NODES 50000
#define N_EDGES 1600000
#define D_IN    3000
#define F1      256
#define F2      128
#define F3      64

// ---------------- scratch (static device arrays; alloc-free rule) ----------
__device__ float g_h[(size_t)N_NODES * F1];    // GEMM output h (per layer)
__device__ float g_agg[(size_t)N_NODES * F1];  // aggregation buffer
__device__ float g_dis[N_NODES];               // deg -> rsqrt(deg)
__device__ int   g_src[N_EDGES];
__device__ int   g_dst[N_EDGES];
__device__ float g_w[N_EDGES];
__device__ int   g_is64;                       // 1 if edge_index arrived as int64

// ---------------- dtype probe ------------------------------------------------
// int64 little-endian indices in [0,50000) => every odd 32-bit word is 0.
// int32 indices => odd words are random node ids (never all zero over 2048).
__global__ void k_probe(const int* __restrict__ ei32) {
    __shared__ int bad;
    if (threadIdx.x == 0) bad = 0;
    __syncthreads();
    for (int i = threadIdx.x; i < 2048; i += blockDim.x) {
        if (ei32[2 * i + 1] != 0) atomicOr(&bad, 1);
    }
    __syncthreads();
    if (threadIdx.x == 0) g_is64 = bad ? 0 : 1;
}

__device__ __forceinline__ int load_idx(const int* __restrict__ ei32, long long pos) {
    int v = g_is64 ? ei32[2 * pos] : ei32[pos];
    // defensive clamp: no input can ever form a wild address
    v = v < 0 ? 0 : (v >= N_NODES ? N_NODES - 1 : v);
    return v;
}

// ---------------- degree / normalization -----------------------------------
__global__ void k_deg_init() {
    int i = blockIdx.x * blockDim.x + threadIdx.x;
    if (i < N_NODES) g_dis[i] = 1.0f;          // self-loop: deg = 1 + indeg
}

__global__ void k_deg_count(const int* __restrict__ ei32) {
    int e = blockIdx.x * blockDim.x + threadIdx.x;
    if (e < N_EDGES) {
        int d = load_idx(ei32, (long long)N_EDGES + e);
        atomicAdd(&g_dis[d], 1.0f);
    }
}

__global__ void k_rsqrt() {
    int i = blockIdx.x * blockDim.x + threadIdx.x;
    if (i < N_NODES) g_dis[i] = rsqrtf(g_dis[i]);
}

__global__ void k_edge_prep(const int* __restrict__ ei32) {
    int e = blockIdx.x * blockDim.x + threadIdx.x;
    if (e < N_EDGES) {
        int s = load_idx(ei32, e);
        int d = load_idx(ei32, (long long)N_EDGES + e);
        g_src[e] = s;
        g_dst[e] = d;
        g_w[e]   = g_dis[s] * g_dis[d];
    }
}

// ---------------- tiled fp32 GEMM: g_h[M,Nc] = op(A)[M,K] @ B[K,Nc] --------
// BM=128, BN=64, BK=8, 256 threads, 8x4 per-thread microtile.
template <bool RELU_A, bool A_FROM_AGG>
__global__ __launch_bounds__(256)
void k_gemm(const float* __restrict__ Aparam, const float* __restrict__ B,
            int M, int K, int Nc) {
    const float* A = A_FROM_AGG ? g_agg : Aparam;
    float* C = g_h;

    const int BM = 128, BN = 64, BK = 8;
    __shared__ float As[BK][BM];
    __shared__ float Bs[BK][BN];

    int tid = threadIdx.x;
    int m0 = blockIdx.x * BM;
    int n0 = blockIdx.y * BN;

    int ty = tid >> 4;        // 0..15 -> row group of 8
    int tx = tid & 15;        // 0..15 -> col group of 4

    int arow = tid >> 1;          // 0..127
    int akc  = (tid & 1) * 4;     // 0 or 4

    float acc[8][4];
#pragma unroll
    for (int i = 0; i < 8; i++)
#pragma unroll
        for (int j = 0; j < 4; j++) acc[i][j] = 0.0f;

    for (int k0 = 0; k0 < K; k0 += BK) {
        {
            int gm = m0 + arow;
            float4 v = make_float4(0.f, 0.f, 0.f, 0.f);
            if (gm < M)
                v = *reinterpret_cast<const float4*>(
                        &A[(long long)gm * K + k0 + akc]);
            if (RELU_A) {
                v.x = fmaxf(v.x, 0.f); v.y = fmaxf(v.y, 0.f);
                v.z = fmaxf(v.z, 0.f); v.w = fmaxf(v.w, 0.f);
            }
            As[akc + 0][arow] = v.x;
            As[akc + 1][arow] = v.y;
            As[akc + 2][arow] = v.z;
            As[akc + 3][arow] = v.w;
        }
        if (tid < 128) {
            int br = tid >> 4;            // 0..7
            int bc = (tid & 15) * 4;      // 0..60
            float4 v = *reinterpret_cast<const float4*>(
                &B[(long long)(k0 + br) * Nc + n0 + bc]);
            *reinterpret_cast<float4*>(&Bs[br][bc]) = v;
        }
        __syncthreads();

#pragma unroll
        for (int k = 0; k < BK; k++) {
            float a[8];
#pragma unroll
            for (int i = 0; i < 8; i++) a[i] = As[k][ty * 8 + i];
            float4 bv = *reinterpret_cast<float4*>(&Bs[k][tx * 4]);
            float b[4] = {bv.x, bv.y, bv.z, bv.w};
#pragma unroll
            for (int i = 0; i < 8; i++)
#pragma unroll
                for (int j = 0; j < 4; j++) acc[i][j] += a[i] * b[j];
        }
        __syncthreads();
    }

#pragma unroll
    for (int i = 0; i < 8; i++) {
        int gm = m0 + ty * 8 + i;
        if (gm < M) {
            float4 o = make_float4(acc[i][0], acc[i][1], acc[i][2], acc[i][3]);
            *reinterpret_cast<float4*>(&C[(long long)gm * Nc + n0 + tx * 4]) = o;
        }
    }
}

// ---------------- agg init: agg = h * dis^2 + bias --------------------------
template <int F, bool EXT_OUT>
__global__ void k_init_agg(const float* __restrict__ bias,
                           float* __restrict__ out_ext) {
    int idx = blockIdx.x * blockDim.x + threadIdx.x;
    const int total = N_NODES * F;
    if (idx >= total) return;
    float* out = EXT_OUT ? out_ext : g_agg;
    int i = idx / F;
    int f = idx - i * F;
    float d = g_dis[i];
    out[idx] = g_h[idx] * d * d + bias[f];
}

// ---------------- edge scatter: agg[dst] += w * h[src] ----------------------
// One thread per (edge, feature); F consecutive threads share an edge, so the
// gather from g_h and the atomics to agg are contiguous per warp.
template <int F, bool EXT_OUT>
__global__ void k_scatter(float* __restrict__ out_ext) {
    long long idx = (long long)blockIdx.x * blockDim.x + threadIdx.x;
    const long long total = (long long)N_EDGES * F;
    if (idx >= total) return;
    float* agg = EXT_OUT ? out_ext : g_agg;
    int e = (int)(idx >> __popc(F - 1));        // idx / F (F is a power of 2)
    int c = (int)(idx & (F - 1));
    int s = g_src[e];
    int d = g_dst[e];
    float w = g_w[e];
    float v = g_h[(long long)s * F + c] * w;
    atomicAdd(&agg[(long long)d * F + c], v);
}

// ---------------- head: out = sigmoid(x3 @ Wl + bl) -------------------------
__global__ void k_final(const float* __restrict__ x3,
                        const float* __restrict__ Wl,
                        const float* __restrict__ bl,
                        float* __restrict__ out) {
    int i = blockIdx.x * blockDim.x + threadIdx.x;
    if (i >= N_NODES) return;
    float s = 0.f;
#pragma unroll
    for (int k = 0; k < F3; k += 4) {
        float4 a = *reinterpret_cast<const float4*>(&x3[(long long)i * F3 + k]);
        float4 w = *reinterpret_cast<const float4*>(&Wl[k]);
        s += a.x * w.x + a.y * w.y + a.z * w.z + a.w * w.w;
    }
    s += bl[0];
    out[i] = 1.0f / (1.0f + expf(-s));
}

// ---------------- launcher ---------------------------------------------------
extern "C" void kernel_launch(void* const* d_in, const int* in_sizes, int n_in,
                              void* d_out, int out_size) {
    const float* x    = (const float*)d_in[0];
    const int*   ei32 = (const int*)d_in[1];   // works for int32 OR int64 input
    const float* W1 = (const float*)d_in[2];
    const float* b1 = (const float*)d_in[3];
    const float* W2 = (const float*)d_in[4];
    const float* b2 = (const float*)d_in[5];
    const float* W3 = (const float*)d_in[6];
    const float* b3 = (const float*)d_in[7];
    const float* Wl = (const float*)d_in[8];
    const float* bl = (const float*)d_in[9];

    float* out = (float*)d_out;          // [N] sigmoid output first
    float* x3  = out + N_NODES;          // [N, 64] second output region

    const int T = 256;
    dim3 blk(T);

    // dtype probe + degree / normalization / edge weights
    k_probe<<<1, blk>>>(ei32);
    k_deg_init<<<(N_NODES + T - 1) / T, blk>>>();
    k_deg_count<<<(N_EDGES + T - 1) / T, blk>>>(ei32);
    k_rsqrt<<<(N_NODES + T - 1) / T, blk>>>();
    k_edge_prep<<<(N_EDGES + T - 1) / T, blk>>>(ei32);

    // ---- layer 1: 3000 -> 256 ----
    {
        dim3 grid((N_NODES + 127) / 128, F1 / 64);
        k_gemm<false, false><<<grid, blk>>>(x, W1, N_NODES, D_IN, F1);
        k_init_agg<F1, false><<<(N_NODES * F1 + T - 1) / T, blk>>>(b1, nullptr);
        long long tot = (long long)N_EDGES * F1;
        k_scatter<F1, false><<<(unsigned)((tot + T - 1) / T), blk>>>(nullptr);
        // ReLU fused into next GEMM's A-load
    }

    // ---- layer 2: 256 -> 128 ----
    {
        dim3 grid((N_NODES + 127) / 128, F2 / 64);
        k_gemm<true, true><<<grid, blk>>>(nullptr, W2, N_NODES, F1, F2);
        k_init_agg<F2, false><<<(N_NODES * F2 + T - 1) / T, blk>>>(b2, nullptr);
        long long tot = (long long)N_EDGES * F2;
        k_scatter<F2, false><<<(unsigned)((tot + T - 1) / T), blk>>>(nullptr);
    }

    // ---- layer 3: 128 -> 64 (agg lands directly in the x3 output region) ----
    {
        dim3 grid((N_NODES + 127) / 128, F3 / 64);
        k_gemm<false, true><<<grid, blk>>>(nullptr, W3, N_NODES, F2, F3);
        k_init_agg<F3, true><<<(N_NODES * F3 + T - 1) / T, blk>>>(b3, x3);
        long long tot = (long long)N_EDGES * F3;
        k_scatter<F3, true><<<(unsigned)((tot + T - 1) / T), blk>>>(x3);
    }

    // ---- head ----
    k_final<<<(N_NODES + T - 1) / T, blk>>>(x3, Wl, bl, out);
}

// round 4
// speedup vs baseline: 1.3881x; 1.3881x over previous
#include <cuda_runtime.h>
#include <cstdint>

#define N_NODES 50000
#define N_EDGES 1600000
#define D_IN    3000
#define F1      256
#define F2      128
#define F3      64

// ---------------- scratch (static device arrays; alloc-free rule) ----------
__device__ float g_h[(size_t)N_NODES * F1];    // GEMM output h (per layer)
__device__ float g_agg[(size_t)N_NODES * F1];  // aggregation buffer
__device__ float g_dis[N_NODES];               // deg -> rsqrt(deg)
__device__ int   g_src[N_EDGES];
__device__ int   g_dst[N_EDGES];
__device__ float g_w[N_EDGES];
__device__ int   g_is64;                       // 1 if edge_index arrived as int64

// ---------------- dtype probe ------------------------------------------------
__global__ void k_probe(const int* __restrict__ ei32) {
    __shared__ int bad;
    if (threadIdx.x == 0) bad = 0;
    __syncthreads();
    for (int i = threadIdx.x; i < 2048; i += blockDim.x) {
        if (ei32[2 * i + 1] != 0) atomicOr(&bad, 1);
    }
    __syncthreads();
    if (threadIdx.x == 0) g_is64 = bad ? 0 : 1;
}

__device__ __forceinline__ int load_idx(const int* __restrict__ ei32, long long pos) {
    int v = g_is64 ? ei32[2 * pos] : ei32[pos];
    v = v < 0 ? 0 : (v >= N_NODES ? N_NODES - 1 : v);
    return v;
}

// ---------------- degree / normalization -----------------------------------
__global__ void k_deg_init() {
    int i = blockIdx.x * blockDim.x + threadIdx.x;
    if (i < N_NODES) g_dis[i] = 1.0f;          // self-loop: deg = 1 + indeg
}

__global__ void k_deg_count(const int* __restrict__ ei32) {
    int e = blockIdx.x * blockDim.x + threadIdx.x;
    if (e < N_EDGES) {
        int d = load_idx(ei32, (long long)N_EDGES + e);
        atomicAdd(&g_dis[d], 1.0f);
    }
}

__global__ void k_rsqrt() {
    int i = blockIdx.x * blockDim.x + threadIdx.x;
    if (i < N_NODES) g_dis[i] = rsqrtf(g_dis[i]);
}

__global__ void k_edge_prep(const int* __restrict__ ei32) {
    int e = blockIdx.x * blockDim.x + threadIdx.x;
    if (e < N_EDGES) {
        int s = load_idx(ei32, e);
        int d = load_idx(ei32, (long long)N_EDGES + e);
        g_src[e] = s;
        g_dst[e] = d;
        g_w[e]   = g_dis[s] * g_dis[d];
    }
}

// ---------------- TF32 helpers ----------------------------------------------
__device__ __forceinline__ uint32_t f2tf32(float x) {
    uint32_t r;
    asm("cvt.rna.tf32.f32 %0, %1;" : "=r"(r) : "f"(x));
    return r;
}

__device__ __forceinline__ void mma_tf32(float& c0, float& c1, float& c2, float& c3,
                                         uint32_t a0, uint32_t a1, uint32_t a2, uint32_t a3,
                                         uint32_t b0, uint32_t b1) {
    asm volatile(
        "mma.sync.aligned.m16n8k8.row.col.f32.tf32.tf32.f32 "
        "{%0,%1,%2,%3}, {%4,%5,%6,%7}, {%8,%9}, {%0,%1,%2,%3};"
        : "+f"(c0), "+f"(c1), "+f"(c2), "+f"(c3)
        : "r"(a0), "r"(a1), "r"(a2), "r"(a3), "r"(b0), "r"(b1));
}

// ---------------- GEMM1: g_h[M,256] = x[M,3000] @ W1[3000,256] (tf32 MMA) ---
// BM=128, BN=128, BK=16; 256 threads = 8 warps (4 in M, 2 in N);
// warp tile 32x64; m16n8k8 -> 2 m-tiles, 8 n-tiles, 2 k-steps per BK.
__global__ __launch_bounds__(256)
void k_gemm1_tf32(const float* __restrict__ A, const float* __restrict__ B) {
    const int BM = 128, BN = 128, BK = 16, LDS_S = 132;
    __shared__ uint32_t As[BK][LDS_S];   // [k][m]
    __shared__ uint32_t Bs[BK][LDS_S];   // [k][n]

    const int tid  = threadIdx.x;
    const int m0   = blockIdx.x * BM;
    const int n0   = blockIdx.y * BN;
    const int warp = tid >> 5, lane = tid & 31;
    const int wm = (warp & 3) * 32;   // warp row offset in tile
    const int wn = (warp >> 2) * 64;  // warp col offset in tile
    const int grp = lane >> 2, t4 = lane & 3;

    float acc[2][8][4];
#pragma unroll
    for (int i = 0; i < 2; i++)
#pragma unroll
        for (int j = 0; j < 8; j++)
#pragma unroll
            for (int q = 0; q < 4; q++) acc[i][j][q] = 0.0f;

    // A-load mapping: float4 id f in [0,512): row=f>>2, kc=(f&3)*4 (two per thread)
    int arow[2], akc[2];
    const float* aptr[2];
    bool aval[2];
#pragma unroll
    for (int i = 0; i < 2; i++) {
        int f = tid + i * 256;
        arow[i] = f >> 2;
        akc[i]  = (f & 3) * 4;
        int gm  = m0 + arow[i];
        aval[i] = (gm < N_NODES);
        aptr[i] = A + (long long)(aval[i] ? gm : 0) * D_IN;
    }
    // B-load mapping: float4 id f: row=f>>5, c=(f&31)*4 (two per thread)
    int brow[2], bc[2];
#pragma unroll
    for (int i = 0; i < 2; i++) {
        int f = tid + i * 256;
        brow[i] = f >> 5;
        bc[i]   = (f & 31) * 4;
    }

    for (int k0 = 0; k0 < D_IN; k0 += BK) {
#pragma unroll
        for (int i = 0; i < 2; i++) {
            float4 v = make_float4(0.f, 0.f, 0.f, 0.f);
            if (aval[i] && (k0 + akc[i] < D_IN))
                v = *reinterpret_cast<const float4*>(aptr[i] + k0 + akc[i]);
            As[akc[i] + 0][arow[i]] = f2tf32(v.x);
            As[akc[i] + 1][arow[i]] = f2tf32(v.y);
            As[akc[i] + 2][arow[i]] = f2tf32(v.z);
            As[akc[i] + 3][arow[i]] = f2tf32(v.w);
        }
#pragma unroll
        for (int i = 0; i < 2; i++) {
            float4 v = make_float4(0.f, 0.f, 0.f, 0.f);
            if (k0 + brow[i] < D_IN)
                v = *reinterpret_cast<const float4*>(
                        &B[(long long)(k0 + brow[i]) * F1 + n0 + bc[i]]);
            uint4 u;
            u.x = f2tf32(v.x); u.y = f2tf32(v.y);
            u.z = f2tf32(v.z); u.w = f2tf32(v.w);
            *reinterpret_cast<uint4*>(&Bs[brow[i]][bc[i]]) = u;
        }
        __syncthreads();

#pragma unroll
        for (int kb = 0; kb < BK; kb += 8) {
            uint32_t af[2][4], bf[8][2];
#pragma unroll
            for (int mt = 0; mt < 2; mt++) {
                int r = wm + mt * 16 + grp;
                af[mt][0] = As[kb + t4][r];
                af[mt][1] = As[kb + t4][r + 8];
                af[mt][2] = As[kb + t4 + 4][r];
                af[mt][3] = As[kb + t4 + 4][r + 8];
            }
#pragma unroll
            for (int nt = 0; nt < 8; nt++) {
                int c = wn + nt * 8 + grp;
                bf[nt][0] = Bs[kb + t4][c];
                bf[nt][1] = Bs[kb + t4 + 4][c];
            }
#pragma unroll
            for (int mt = 0; mt < 2; mt++)
#pragma unroll
                for (int nt = 0; nt < 8; nt++)
                    mma_tf32(acc[mt][nt][0], acc[mt][nt][1],
                             acc[mt][nt][2], acc[mt][nt][3],
                             af[mt][0], af[mt][1], af[mt][2], af[mt][3],
                             bf[nt][0], bf[nt][1]);
        }
        __syncthreads();
    }

    // store: c0,c1 at (row, col..col+1); c2,c3 at (row+8, ...)
#pragma unroll
    for (int mt = 0; mt < 2; mt++) {
        int row = m0 + wm + mt * 16 + grp;
#pragma unroll
        for (int nt = 0; nt < 8; nt++) {
            int col = n0 + wn + nt * 8 + 2 * t4;
            if (row < N_NODES) {
                float2 v01 = make_float2(acc[mt][nt][0], acc[mt][nt][1]);
                *reinterpret_cast<float2*>(&g_h[(long long)row * F1 + col]) = v01;
            }
            if (row + 8 < N_NODES) {
                float2 v23 = make_float2(acc[mt][nt][2], acc[mt][nt][3]);
                *reinterpret_cast<float2*>(&g_h[(long long)(row + 8) * F1 + col]) = v23;
            }
        }
    }
}

// ---------------- tiled fp32 GEMM (layers 2/3): g_h = op(A) @ B -------------
template <bool RELU_A, bool A_FROM_AGG>
__global__ __launch_bounds__(256)
void k_gemm(const float* __restrict__ Aparam, const float* __restrict__ B,
            int M, int K, int Nc) {
    const float* A = A_FROM_AGG ? g_agg : Aparam;
    float* C = g_h;

    const int BM = 128, BN = 64, BK = 8;
    __shared__ float As[BK][BM];
    __shared__ float Bs[BK][BN];

    int tid = threadIdx.x;
    int m0 = blockIdx.x * BM;
    int n0 = blockIdx.y * BN;

    int ty = tid >> 4;
    int tx = tid & 15;

    int arow = tid >> 1;
    int akc  = (tid & 1) * 4;

    float acc[8][4];
#pragma unroll
    for (int i = 0; i < 8; i++)
#pragma unroll
        for (int j = 0; j < 4; j++) acc[i][j] = 0.0f;

    for (int k0 = 0; k0 < K; k0 += BK) {
        {
            int gm = m0 + arow;
            float4 v = make_float4(0.f, 0.f, 0.f, 0.f);
            if (gm < M)
                v = *reinterpret_cast<const float4*>(
                        &A[(long long)gm * K + k0 + akc]);
            if (RELU_A) {
                v.x = fmaxf(v.x, 0.f); v.y = fmaxf(v.y, 0.f);
                v.z = fmaxf(v.z, 0.f); v.w = fmaxf(v.w, 0.f);
            }
            As[akc + 0][arow] = v.x;
            As[akc + 1][arow] = v.y;
            As[akc + 2][arow] = v.z;
            As[akc + 3][arow] = v.w;
        }
        if (tid < 128) {
            int br = tid >> 4;
            int bc2 = (tid & 15) * 4;
            float4 v = *reinterpret_cast<const float4*>(
                &B[(long long)(k0 + br) * Nc + n0 + bc2]);
            *reinterpret_cast<float4*>(&Bs[br][bc2]) = v;
        }
        __syncthreads();

#pragma unroll
        for (int k = 0; k < BK; k++) {
            float a[8];
#pragma unroll
            for (int i = 0; i < 8; i++) a[i] = As[k][ty * 8 + i];
            float4 bv = *reinterpret_cast<float4*>(&Bs[k][tx * 4]);
            float b[4] = {bv.x, bv.y, bv.z, bv.w};
#pragma unroll
            for (int i = 0; i < 8; i++)
#pragma unroll
                for (int j = 0; j < 4; j++) acc[i][j] += a[i] * b[j];
        }
        __syncthreads();
    }

#pragma unroll
    for (int i = 0; i < 8; i++) {
        int gm = m0 + ty * 8 + i;
        if (gm < M) {
            float4 o = make_float4(acc[i][0], acc[i][1], acc[i][2], acc[i][3]);
            *reinterpret_cast<float4*>(&C[(long long)gm * Nc + n0 + tx * 4]) = o;
        }
    }
}

// ---------------- agg init: agg = h * dis^2 + bias --------------------------
template <int F, bool EXT_OUT>
__global__ void k_init_agg(const float* __restrict__ bias,
                           float* __restrict__ out_ext) {
    int idx = blockIdx.x * blockDim.x + threadIdx.x;
    const int total = N_NODES * F;
    if (idx >= total) return;
    float* out = EXT_OUT ? out_ext : g_agg;
    int i = idx / F;
    int f = idx - i * F;
    float d = g_dis[i];
    out[idx] = g_h[idx] * d * d + bias[f];
}

// ---------------- edge scatter: agg[dst] += w * h[src] ----------------------
template <int F, bool EXT_OUT>
__global__ void k_scatter(float* __restrict__ out_ext) {
    long long idx = (long long)blockIdx.x * blockDim.x + threadIdx.x;
    const long long total = (long long)N_EDGES * F;
    if (idx >= total) return;
    float* agg = EXT_OUT ? out_ext : g_agg;
    int e = (int)(idx >> __popc(F - 1));        // idx / F (F power of 2)
    int c = (int)(idx & (F - 1));
    int s = g_src[e];
    int d = g_dst[e];
    float w = g_w[e];
    float v = g_h[(long long)s * F + c] * w;
    atomicAdd(&agg[(long long)d * F + c], v);
}

// ---------------- head: out = sigmoid(x3 @ Wl + bl) -------------------------
__global__ void k_final(const float* __restrict__ x3,
                        const float* __restrict__ Wl,
                        const float* __restrict__ bl,
                        float* __restrict__ out) {
    int i = blockIdx.x * blockDim.x + threadIdx.x;
    if (i >= N_NODES) return;
    float s = 0.f;
#pragma unroll
    for (int k = 0; k < F3; k += 4) {
        float4 a = *reinterpret_cast<const float4*>(&x3[(long long)i * F3 + k]);
        float4 w = *reinterpret_cast<const float4*>(&Wl[k]);
        s += a.x * w.x + a.y * w.y + a.z * w.z + a.w * w.w;
    }
    s += bl[0];
    out[i] = 1.0f / (1.0f + expf(-s));
}

// ---------------- launcher ---------------------------------------------------
extern "C" void kernel_launch(void* const* d_in, const int* in_sizes, int n_in,
                              void* d_out, int out_size) {
    const float* x    = (const float*)d_in[0];
    const int*   ei32 = (const int*)d_in[1];
    const float* W1 = (const float*)d_in[2];
    const float* b1 = (const float*)d_in[3];
    const float* W2 = (const float*)d_in[4];
    const float* b2 = (const float*)d_in[5];
    const float* W3 = (const float*)d_in[6];
    const float* b3 = (const float*)d_in[7];
    const float* Wl = (const float*)d_in[8];
    const float* bl = (const float*)d_in[9];

    float* out = (float*)d_out;          // [N] sigmoid output first
    float* x3  = out + N_NODES;          // [N, 64] second output region

    const int T = 256;
    dim3 blk(T);

    k_probe<<<1, blk>>>(ei32);
    k_deg_init<<<(N_NODES + T - 1) / T, blk>>>();
    k_deg_count<<<(N_EDGES + T - 1) / T, blk>>>(ei32);
    k_rsqrt<<<(N_NODES + T - 1) / T, blk>>>();
    k_edge_prep<<<(N_EDGES + T - 1) / T, blk>>>(ei32);

    // ---- layer 1: 3000 -> 256 (tf32 tensor-core GEMM) ----
    {
        dim3 grid((N_NODES + 127) / 128, F1 / 128);
        k_gemm1_tf32<<<grid, blk>>>(x, W1);
        k_init_agg<F1, false><<<(N_NODES * F1 + T - 1) / T, blk>>>(b1, nullptr);
        long long tot = (long long)N_EDGES * F1;
        k_scatter<F1, false><<<(unsigned)((tot + T - 1) / T), blk>>>(nullptr);
    }

    // ---- layer 2: 256 -> 128 ----
    {
        dim3 grid((N_NODES + 127) / 128, F2 / 64);
        k_gemm<true, true><<<grid, blk>>>(nullptr, W2, N_NODES, F1, F2);
        k_init_agg<F2, false><<<(N_NODES * F2 + T - 1) / T, blk>>>(b2, nullptr);
        long long tot = (long long)N_EDGES * F2;
        k_scatter<F2, false><<<(unsigned)((tot + T - 1) / T), blk>>>(nullptr);
    }

    // ---- layer 3: 128 -> 64 ----
    {
        dim3 grid((N_NODES + 127) / 128, F3 / 64);
        k_gemm<false, true><<<grid, blk>>>(nullptr, W3, N_NODES, F2, F3);
        k_init_agg<F3, true><<<(N_NODES * F3 + T - 1) / T, blk>>>(b3, x3);
        long long tot = (long long)N_EDGES * F3;
        k_scatter<F3, true><<<(unsigned)((tot + T - 1) / T), blk>>>(x3);
    }

    k_final<<<(N_NODES + T - 1) / T, blk>>>(x3, Wl, bl, out);
}

// round 5
// speedup vs baseline: 2.6472x; 1.9071x over previous
#include <cuda_runtime.h>
#include <cstdint>

#define N_NODES 50000
#define N_EDGES 1600000
#define D_IN    3000
#define F1      256
#define F2      128
#define F3      64

// ---------------- scratch (static device arrays; alloc-free rule) ----------
__device__ float g_h[(size_t)N_NODES * F1];    // GEMM output h (per layer)
__device__ float g_agg[(size_t)N_NODES * F1];  // aggregation buffer
__device__ float g_dis[N_NODES];               // deg -> rsqrt(deg)
__device__ int   g_src[N_EDGES];
__device__ int   g_dst[N_EDGES];
__device__ float g_w[N_EDGES];
__device__ int   g_is64;                       // 1 if edge_index arrived as int64

// ---------------- dtype probe ------------------------------------------------
__global__ void k_probe(const int* __restrict__ ei32) {
    __shared__ int bad;
    if (threadIdx.x == 0) bad = 0;
    __syncthreads();
    for (int i = threadIdx.x; i < 2048; i += blockDim.x) {
        if (ei32[2 * i + 1] != 0) atomicOr(&bad, 1);
    }
    __syncthreads();
    if (threadIdx.x == 0) g_is64 = bad ? 0 : 1;
}

__device__ __forceinline__ int load_idx(const int* __restrict__ ei32, long long pos) {
    int v = g_is64 ? ei32[2 * pos] : ei32[pos];
    v = v < 0 ? 0 : (v >= N_NODES ? N_NODES - 1 : v);
    return v;
}

// ---------------- degree / normalization -----------------------------------
__global__ void k_deg_init() {
    int i = blockIdx.x * blockDim.x + threadIdx.x;
    if (i < N_NODES) g_dis[i] = 1.0f;          // self-loop: deg = 1 + indeg
}

__global__ void k_deg_count(const int* __restrict__ ei32) {
    int e = blockIdx.x * blockDim.x + threadIdx.x;
    if (e < N_EDGES) {
        int d = load_idx(ei32, (long long)N_EDGES + e);
        atomicAdd(&g_dis[d], 1.0f);
    }
}

__global__ void k_rsqrt() {
    int i = blockIdx.x * blockDim.x + threadIdx.x;
    if (i < N_NODES) g_dis[i] = rsqrtf(g_dis[i]);
}

__global__ void k_edge_prep(const int* __restrict__ ei32) {
    int e = blockIdx.x * blockDim.x + threadIdx.x;
    if (e < N_EDGES) {
        int s = load_idx(ei32, e);
        int d = load_idx(ei32, (long long)N_EDGES + e);
        g_src[e] = s;
        g_dst[e] = d;
        g_w[e]   = g_dis[s] * g_dis[d];
    }
}

// ---------------- TF32 helpers ----------------------------------------------
__device__ __forceinline__ uint32_t f2tf32(float x) {
    uint32_t r;
    asm("cvt.rna.tf32.f32 %0, %1;" : "=r"(r) : "f"(x));
    return r;
}

__device__ __forceinline__ void mma_tf32(float& c0, float& c1, float& c2, float& c3,
                                         uint32_t a0, uint32_t a1, uint32_t a2, uint32_t a3,
                                         uint32_t b0, uint32_t b1) {
    asm volatile(
        "mma.sync.aligned.m16n8k8.row.col.f32.tf32.tf32.f32 "
        "{%0,%1,%2,%3}, {%4,%5,%6,%7}, {%8,%9}, {%0,%1,%2,%3};"
        : "+f"(c0), "+f"(c1), "+f"(c2), "+f"(c3)
        : "r"(a0), "r"(a1), "r"(a2), "r"(a3), "r"(b0), "r"(b1));
}

// ---------------- GEMM1: g_h[M,256] = x[M,3000] @ W1[3000,256] (tf32 MMA) ---
// BM=128, BN=128, BK=16; 256 threads = 8 warps (4 in M, 2 in N);
// warp tile 32x64. Double-buffered SMEM + register prefetch (1 sync/iter).
// Grid: x = n-tile (2), y = m-tile (391) so concurrent blocks share A via L2.
__global__ __launch_bounds__(256)
void k_gemm1_tf32(const float* __restrict__ A, const float* __restrict__ B) {
    const int BM = 128, BK = 16, LDS_S = 132;
    __shared__ uint32_t As[2][BK][LDS_S];   // [buf][k][m]
    __shared__ uint32_t Bs[2][BK][LDS_S];   // [buf][k][n]

    const int tid  = threadIdx.x;
    const int m0   = blockIdx.y * BM;
    const int n0   = blockIdx.x * 128;
    const int warp = tid >> 5, lane = tid & 31;
    const int wm = (warp & 3) * 32;
    const int wn = (warp >> 2) * 64;
    const int grp = lane >> 2, t4 = lane & 3;

    float acc[2][8][4];
#pragma unroll
    for (int i = 0; i < 2; i++)
#pragma unroll
        for (int j = 0; j < 8; j++)
#pragma unroll
            for (int q = 0; q < 4; q++) acc[i][j][q] = 0.0f;

    // A-load mapping: float4 id f in [0,512): row=f>>2, kc=(f&3)*4
    int arow[2], akc[2];
    const float* aptr[2];
    bool aval[2];
#pragma unroll
    for (int i = 0; i < 2; i++) {
        int f = tid + i * 256;
        arow[i] = f >> 2;
        akc[i]  = (f & 3) * 4;
        int gm  = m0 + arow[i];
        aval[i] = (gm < N_NODES);
        aptr[i] = A + (long long)(aval[i] ? gm : 0) * D_IN;
    }
    // B-load mapping: float4 id f: row=f>>5, c=(f&31)*4
    int brow[2], bcl[2];
#pragma unroll
    for (int i = 0; i < 2; i++) {
        int f = tid + i * 256;
        brow[i] = f >> 5;
        bcl[i]  = (f & 31) * 4;
    }

    const int NK = (D_IN + BK - 1) / BK;   // 188 (last tile partial, zero-filled)

    float4 ra[2], rb[2];
    auto load_tiles = [&](int k0) {
#pragma unroll
        for (int i = 0; i < 2; i++) {
            ra[i] = make_float4(0.f, 0.f, 0.f, 0.f);
            if (aval[i] && (k0 + akc[i] < D_IN))
                ra[i] = *reinterpret_cast<const float4*>(aptr[i] + k0 + akc[i]);
        }
#pragma unroll
        for (int i = 0; i < 2; i++) {
            rb[i] = make_float4(0.f, 0.f, 0.f, 0.f);
            if (k0 + brow[i] < D_IN)
                rb[i] = *reinterpret_cast<const float4*>(
                            &B[(long long)(k0 + brow[i]) * F1 + n0 + bcl[i]]);
        }
    };
    auto store_tiles = [&](int buf) {
#pragma unroll
        for (int i = 0; i < 2; i++) {
            As[buf][akc[i] + 0][arow[i]] = f2tf32(ra[i].x);
            As[buf][akc[i] + 1][arow[i]] = f2tf32(ra[i].y);
            As[buf][akc[i] + 2][arow[i]] = f2tf32(ra[i].z);
            As[buf][akc[i] + 3][arow[i]] = f2tf32(ra[i].w);
        }
#pragma unroll
        for (int i = 0; i < 2; i++) {
            uint4 u;
            u.x = f2tf32(rb[i].x); u.y = f2tf32(rb[i].y);
            u.z = f2tf32(rb[i].z); u.w = f2tf32(rb[i].w);
            *reinterpret_cast<uint4*>(&Bs[buf][brow[i]][bcl[i]]) = u;
        }
    };

    load_tiles(0);
    store_tiles(0);
    __syncthreads();

    for (int it = 0; it < NK; it++) {
        int buf = it & 1;
        if (it + 1 < NK) load_tiles((it + 1) * BK);

#pragma unroll
        for (int kb = 0; kb < BK; kb += 8) {
            uint32_t af[2][4], bf[8][2];
#pragma unroll
            for (int mt = 0; mt < 2; mt++) {
                int r = wm + mt * 16 + grp;
                af[mt][0] = As[buf][kb + t4][r];
                af[mt][1] = As[buf][kb + t4][r + 8];
                af[mt][2] = As[buf][kb + t4 + 4][r];
                af[mt][3] = As[buf][kb + t4 + 4][r + 8];
            }
#pragma unroll
            for (int nt = 0; nt < 8; nt++) {
                int c = wn + nt * 8 + grp;
                bf[nt][0] = Bs[buf][kb + t4][c];
                bf[nt][1] = Bs[buf][kb + t4 + 4][c];
            }
#pragma unroll
            for (int mt = 0; mt < 2; mt++)
#pragma unroll
                for (int nt = 0; nt < 8; nt++)
                    mma_tf32(acc[mt][nt][0], acc[mt][nt][1],
                             acc[mt][nt][2], acc[mt][nt][3],
                             af[mt][0], af[mt][1], af[mt][2], af[mt][3],
                             bf[nt][0], bf[nt][1]);
        }

        if (it + 1 < NK) store_tiles(buf ^ 1);
        __syncthreads();
    }

    // store: c0,c1 at (row, col..col+1); c2,c3 at (row+8, ...)
#pragma unroll
    for (int mt = 0; mt < 2; mt++) {
        int row = m0 + wm + mt * 16 + grp;
#pragma unroll
        for (int nt = 0; nt < 8; nt++) {
            int col = n0 + wn + nt * 8 + 2 * t4;
            if (row < N_NODES) {
                float2 v01 = make_float2(acc[mt][nt][0], acc[mt][nt][1]);
                *reinterpret_cast<float2*>(&g_h[(long long)row * F1 + col]) = v01;
            }
            if (row + 8 < N_NODES) {
                float2 v23 = make_float2(acc[mt][nt][2], acc[mt][nt][3]);
                *reinterpret_cast<float2*>(&g_h[(long long)(row + 8) * F1 + col]) = v23;
            }
        }
    }
}

// ---------------- tiled fp32 GEMM (layers 2/3): g_h = op(A) @ B -------------
template <bool RELU_A, bool A_FROM_AGG>
__global__ __launch_bounds__(256)
void k_gemm(const float* __restrict__ Aparam, const float* __restrict__ B,
            int M, int K, int Nc) {
    const float* A = A_FROM_AGG ? g_agg : Aparam;
    float* C = g_h;

    const int BM = 128, BN = 64, BK = 8;
    __shared__ float As[BK][BM];
    __shared__ float Bs[BK][BN];

    int tid = threadIdx.x;
    int m0 = blockIdx.x * BM;
    int n0 = blockIdx.y * BN;

    int ty = tid >> 4;
    int tx = tid & 15;

    int arow = tid >> 1;
    int akc  = (tid & 1) * 4;

    float acc[8][4];
#pragma unroll
    for (int i = 0; i < 8; i++)
#pragma unroll
        for (int j = 0; j < 4; j++) acc[i][j] = 0.0f;

    for (int k0 = 0; k0 < K; k0 += BK) {
        {
            int gm = m0 + arow;
            float4 v = make_float4(0.f, 0.f, 0.f, 0.f);
            if (gm < M)
                v = *reinterpret_cast<const float4*>(
                        &A[(long long)gm * K + k0 + akc]);
            if (RELU_A) {
                v.x = fmaxf(v.x, 0.f); v.y = fmaxf(v.y, 0.f);
                v.z = fmaxf(v.z, 0.f); v.w = fmaxf(v.w, 0.f);
            }
            As[akc + 0][arow] = v.x;
            As[akc + 1][arow] = v.y;
            As[akc + 2][arow] = v.z;
            As[akc + 3][arow] = v.w;
        }
        if (tid < 128) {
            int br = tid >> 4;
            int bc2 = (tid & 15) * 4;
            float4 v = *reinterpret_cast<const float4*>(
                &B[(long long)(k0 + br) * Nc + n0 + bc2]);
            *reinterpret_cast<float4*>(&Bs[br][bc2]) = v;
        }
        __syncthreads();

#pragma unroll
        for (int k = 0; k < BK; k++) {
            float a[8];
#pragma unroll
            for (int i = 0; i < 8; i++) a[i] = As[k][ty * 8 + i];
            float4 bv = *reinterpret_cast<float4*>(&Bs[k][tx * 4]);
            float b[4] = {bv.x, bv.y, bv.z, bv.w};
#pragma unroll
            for (int i = 0; i < 8; i++)
#pragma unroll
                for (int j = 0; j < 4; j++) acc[i][j] += a[i] * b[j];
        }
        __syncthreads();
    }

#pragma unroll
    for (int i = 0; i < 8; i++) {
        int gm = m0 + ty * 8 + i;
        if (gm < M) {
            float4 o = make_float4(acc[i][0], acc[i][1], acc[i][2], acc[i][3]);
            *reinterpret_cast<float4*>(&C[(long long)gm * Nc + n0 + tx * 4]) = o;
        }
    }
}

// ---------------- agg init: agg = h * dis^2 + bias --------------------------
template <int F, bool EXT_OUT>
__global__ void k_init_agg(const float* __restrict__ bias,
                           float* __restrict__ out_ext) {
    int idx = blockIdx.x * blockDim.x + threadIdx.x;
    const int total = N_NODES * F;
    if (idx >= total) return;
    float* out = EXT_OUT ? out_ext : g_agg;
    int i = idx / F;
    int f = idx - i * F;
    float d = g_dis[i];
    out[idx] = g_h[idx] * d * d + bias[f];
}

// ---------------- edge scatter: agg[dst] += w * h[src] (vector red) ---------
// One thread per (edge, float4-chunk); F4 consecutive threads share an edge.
template <int F4, bool EXT_OUT>   // F4 = F/4
__global__ void k_scatter(float* __restrict__ out_ext) {
    long long idx = (long long)blockIdx.x * blockDim.x + threadIdx.x;
    const long long total = (long long)N_EDGES * F4;
    if (idx >= total) return;
    float* agg = EXT_OUT ? out_ext : g_agg;
    int e = (int)(idx >> __popc(F4 - 1));       // idx / F4 (power of 2)
    int c = (int)(idx & (F4 - 1));
    int s = g_src[e];
    int d = g_dst[e];
    float w = g_w[e];
    float4 v = reinterpret_cast<const float4*>(g_h)[(long long)s * F4 + c];
    float* p = agg + ((long long)d * F4 + c) * 4;
    asm volatile("red.global.add.v4.f32 [%0], {%1, %2, %3, %4};"
                 :: "l"(p), "f"(v.x * w), "f"(v.y * w), "f"(v.z * w), "f"(v.w * w)
                 : "memory");
}

// ---------------- head: out = sigmoid(x3 @ Wl + bl) -------------------------
__global__ void k_final(const float* __restrict__ x3,
                        const float* __restrict__ Wl,
                        const float* __restrict__ bl,
                        float* __restrict__ out) {
    int i = blockIdx.x * blockDim.x + threadIdx.x;
    if (i >= N_NODES) return;
    float s = 0.f;
#pragma unroll
    for (int k = 0; k < F3; k += 4) {
        float4 a = *reinterpret_cast<const float4*>(&x3[(long long)i * F3 + k]);
        float4 w = *reinterpret_cast<const float4*>(&Wl[k]);
        s += a.x * w.x + a.y * w.y + a.z * w.z + a.w * w.w;
    }
    s += bl[0];
    out[i] = 1.0f / (1.0f + expf(-s));
}

// ---------------- launcher ---------------------------------------------------
extern "C" void kernel_launch(void* const* d_in, const int* in_sizes, int n_in,
                              void* d_out, int out_size) {
    const float* x    = (const float*)d_in[0];
    const int*   ei32 = (const int*)d_in[1];
    const float* W1 = (const float*)d_in[2];
    const float* b1 = (const float*)d_in[3];
    const float* W2 = (const float*)d_in[4];
    const float* b2 = (const float*)d_in[5];
    const float* W3 = (const float*)d_in[6];
    const float* b3 = (const float*)d_in[7];
    const float* Wl = (const float*)d_in[8];
    const float* bl = (const float*)d_in[9];

    float* out = (float*)d_out;          // [N] sigmoid output first
    float* x3  = out + N_NODES;          // [N, 64] second output region

    const int T = 256;
    dim3 blk(T);

    k_probe<<<1, blk>>>(ei32);
    k_deg_init<<<(N_NODES + T - 1) / T, blk>>>();
    k_deg_count<<<(N_EDGES + T - 1) / T, blk>>>(ei32);
    k_rsqrt<<<(N_NODES + T - 1) / T, blk>>>();
    k_edge_prep<<<(N_EDGES + T - 1) / T, blk>>>(ei32);

    // ---- layer 1: 3000 -> 256 (tf32 tensor-core GEMM) ----
    {
        dim3 grid(F1 / 128, (N_NODES + 127) / 128);   // x = n-tile, y = m-tile
        k_gemm1_tf32<<<grid, blk>>>(x, W1);
        k_init_agg<F1, false><<<(N_NODES * F1 + T - 1) / T, blk>>>(b1, nullptr);
        long long tot = (long long)N_EDGES * (F1 / 4);
        k_scatter<F1 / 4, false><<<(unsigned)((tot + T - 1) / T), blk>>>(nullptr);
    }

    // ---- layer 2: 256 -> 128 ----
    {
        dim3 grid((N_NODES + 127) / 128, F2 / 64);
        k_gemm<true, true><<<grid, blk>>>(nullptr, W2, N_NODES, F1, F2);
        k_init_agg<F2, false><<<(N_NODES * F2 + T - 1) / T, blk>>>(b2, nullptr);
        long long tot = (long long)N_EDGES * (F2 / 4);
        k_scatter<F2 / 4, false><<<(unsigned)((tot + T - 1) / T), blk>>>(nullptr);
    }

    // ---- layer 3: 128 -> 64 ----
    {
        dim3 grid((N_NODES + 127) / 128, F3 / 64);
        k_gemm<false, true><<<grid, blk>>>(nullptr, W3, N_NODES, F2, F3);
        k_init_agg<F3, true><<<(N_NODES * F3 + T - 1) / T, blk>>>(b3, x3);
        long long tot = (long long)N_EDGES * (F3 / 4);
        k_scatter<F3 / 4, true><<<(unsigned)((tot + T - 1) / T), blk>>>(x3);
    }

    k_final<<<(N_NODES + T - 1) / T, blk>>>(x3, Wl, bl, out);
}

// round 6
// speedup vs baseline: 3.3067x; 1.2492x over previous
#include <cuda_runtime.h>
#include <cstdint>

#define N_NODES 50000
#define N_EDGES 1600000
#define D_IN    3000
#define F1      256
#define F2      128
#define F3      64
#define SCAN_NB ((N_NODES + 255) / 256)   // 196

// ---------------- scratch (static device arrays; alloc-free rule) ----------
__device__ float g_h[(size_t)N_NODES * F1];    // GEMM output h (per layer)
__device__ float g_agg[(size_t)N_NODES * F1];  // aggregation buffer
__device__ float g_dis[N_NODES];               // rsqrt(deg)
__device__ int   g_indeg[N_NODES];             // integer in-degree
__device__ int   g_rowptr[N_NODES + 1];        // CSR row pointers (by dst)
__device__ int   g_cursor[N_NODES];            // fill cursors
__device__ int   g_csr_src[N_EDGES];           // CSR: source node per slot
__device__ float g_csr_w[N_EDGES];             // CSR: edge weight per slot
__device__ int   g_blocksum[256];              // scan partials (>= SCAN_NB)
__device__ int   g_is64;                       // 1 if edge_index arrived as int64

// ---------------- dtype probe ------------------------------------------------
__global__ void k_probe(const int* __restrict__ ei32) {
    __shared__ int bad;
    if (threadIdx.x == 0) bad = 0;
    __syncthreads();
    for (int i = threadIdx.x; i < 2048; i += blockDim.x) {
        if (ei32[2 * i + 1] != 0) atomicOr(&bad, 1);
    }
    __syncthreads();
    if (threadIdx.x == 0) g_is64 = bad ? 0 : 1;
}

__device__ __forceinline__ int load_idx(const int* __restrict__ ei32, long long pos) {
    int v = g_is64 ? ei32[2 * pos] : ei32[pos];
    v = v < 0 ? 0 : (v >= N_NODES ? N_NODES - 1 : v);
    return v;
}

// ---------------- degree / CSR build ----------------------------------------
__global__ void k_zero() {
    int i = blockIdx.x * blockDim.x + threadIdx.x;
    if (i < N_NODES) { g_indeg[i] = 0; g_cursor[i] = 0; }
}

__global__ void k_deg_count(const int* __restrict__ ei32) {
    int e = blockIdx.x * blockDim.x + threadIdx.x;
    if (e < N_EDGES) {
        int d = load_idx(ei32, (long long)N_EDGES + e);
        atomicAdd(&g_indeg[d], 1);
    }
}

__global__ void k_rsqrt() {
    int i = blockIdx.x * blockDim.x + threadIdx.x;
    if (i < N_NODES) g_dis[i] = rsqrtf((float)g_indeg[i] + 1.0f);
}

// scan stage 1: per-block inclusive scan of indeg; write to rowptr[i+1],
// block total to g_blocksum[b].
__global__ void k_scan1() {
    __shared__ int s[256];
    int b = blockIdx.x, t = threadIdx.x;
    int i = b * 256 + t;
    int v = (i < N_NODES) ? g_indeg[i] : 0;
    s[t] = v;
    __syncthreads();
#pragma unroll
    for (int off = 1; off < 256; off <<= 1) {
        int add = (t >= off) ? s[t - off] : 0;
        __syncthreads();
        s[t] += add;
        __syncthreads();
    }
    if (i < N_NODES) g_rowptr[i + 1] = s[t];
    if (t == 255) g_blocksum[b] = s[255];
}

// scan stage 2: exclusive scan of block sums (single block).
__global__ void k_scan2() {
    __shared__ int s[256];
    int t = threadIdx.x;
    int v = (t < SCAN_NB) ? g_blocksum[t] : 0;
    s[t] = v;
    __syncthreads();
#pragma unroll
    for (int off = 1; off < 256; off <<= 1) {
        int add = (t >= off) ? s[t - off] : 0;
        __syncthreads();
        s[t] += add;
        __syncthreads();
    }
    g_blocksum[t] = s[t] - v;   // exclusive
}

// scan stage 3: add block offsets; set rowptr[0] = 0.
__global__ void k_scan3() {
    int i = blockIdx.x * blockDim.x + threadIdx.x;
    if (i < N_NODES) g_rowptr[i + 1] += g_blocksum[blockIdx.x];
    if (i == 0) g_rowptr[0] = 0;
}

// fill CSR slots (order within a node nondeterministic; float-add commutes
// up to rounding, same as atomic scatter did).
__global__ void k_fill(const int* __restrict__ ei32) {
    int e = blockIdx.x * blockDim.x + threadIdx.x;
    if (e < N_EDGES) {
        int s = load_idx(ei32, e);
        int d = load_idx(ei32, (long long)N_EDGES + e);
        int pos = g_rowptr[d] + atomicAdd(&g_cursor[d], 1);
        g_csr_src[pos] = s;
        g_csr_w[pos]   = g_dis[s] * g_dis[d];
    }
}

// ---------------- TF32 helpers ----------------------------------------------
__device__ __forceinline__ uint32_t f2tf32(float x) {
    uint32_t r;
    asm("cvt.rna.tf32.f32 %0, %1;" : "=r"(r) : "f"(x));
    return r;
}

__device__ __forceinline__ void mma_tf32(float& c0, float& c1, float& c2, float& c3,
                                         uint32_t a0, uint32_t a1, uint32_t a2, uint32_t a3,
                                         uint32_t b0, uint32_t b1) {
    asm volatile(
        "mma.sync.aligned.m16n8k8.row.col.f32.tf32.tf32.f32 "
        "{%0,%1,%2,%3}, {%4,%5,%6,%7}, {%8,%9}, {%0,%1,%2,%3};"
        : "+f"(c0), "+f"(c1), "+f"(c2), "+f"(c3)
        : "r"(a0), "r"(a1), "r"(a2), "r"(a3), "r"(b0), "r"(b1));
}

// ---------------- GEMM1: g_h[M,256] = x[M,3000] @ W1[3000,256] (tf32 MMA) ---
__global__ __launch_bounds__(256)
void k_gemm1_tf32(const float* __restrict__ A, const float* __restrict__ B) {
    const int BM = 128, BK = 16, LDS_S = 132;
    __shared__ uint32_t As[2][BK][LDS_S];
    __shared__ uint32_t Bs[2][BK][LDS_S];

    const int tid  = threadIdx.x;
    const int m0   = blockIdx.y * BM;
    const int n0   = blockIdx.x * 128;
    const int warp = tid >> 5, lane = tid & 31;
    const int wm = (warp & 3) * 32;
    const int wn = (warp >> 2) * 64;
    const int grp = lane >> 2, t4 = lane & 3;

    float acc[2][8][4];
#pragma unroll
    for (int i = 0; i < 2; i++)
#pragma unroll
        for (int j = 0; j < 8; j++)
#pragma unroll
            for (int q = 0; q < 4; q++) acc[i][j][q] = 0.0f;

    int arow[2], akc[2];
    const float* aptr[2];
    bool aval[2];
#pragma unroll
    for (int i = 0; i < 2; i++) {
        int f = tid + i * 256;
        arow[i] = f >> 2;
        akc[i]  = (f & 3) * 4;
        int gm  = m0 + arow[i];
        aval[i] = (gm < N_NODES);
        aptr[i] = A + (long long)(aval[i] ? gm : 0) * D_IN;
    }
    int brow[2], bcl[2];
#pragma unroll
    for (int i = 0; i < 2; i++) {
        int f = tid + i * 256;
        brow[i] = f >> 5;
        bcl[i]  = (f & 31) * 4;
    }

    const int NK = (D_IN + BK - 1) / BK;

    float4 ra[2], rb[2];
    auto load_tiles = [&](int k0) {
#pragma unroll
        for (int i = 0; i < 2; i++) {
            ra[i] = make_float4(0.f, 0.f, 0.f, 0.f);
            if (aval[i] && (k0 + akc[i] < D_IN))
                ra[i] = *reinterpret_cast<const float4*>(aptr[i] + k0 + akc[i]);
        }
#pragma unroll
        for (int i = 0; i < 2; i++) {
            rb[i] = make_float4(0.f, 0.f, 0.f, 0.f);
            if (k0 + brow[i] < D_IN)
                rb[i] = *reinterpret_cast<const float4*>(
                            &B[(long long)(k0 + brow[i]) * F1 + n0 + bcl[i]]);
        }
    };
    auto store_tiles = [&](int buf) {
#pragma unroll
        for (int i = 0; i < 2; i++) {
            As[buf][akc[i] + 0][arow[i]] = f2tf32(ra[i].x);
            As[buf][akc[i] + 1][arow[i]] = f2tf32(ra[i].y);
            As[buf][akc[i] + 2][arow[i]] = f2tf32(ra[i].z);
            As[buf][akc[i] + 3][arow[i]] = f2tf32(ra[i].w);
        }
#pragma unroll
        for (int i = 0; i < 2; i++) {
            uint4 u;
            u.x = f2tf32(rb[i].x); u.y = f2tf32(rb[i].y);
            u.z = f2tf32(rb[i].z); u.w = f2tf32(rb[i].w);
            *reinterpret_cast<uint4*>(&Bs[buf][brow[i]][bcl[i]]) = u;
        }
    };

    load_tiles(0);
    store_tiles(0);
    __syncthreads();

    for (int it = 0; it < NK; it++) {
        int buf = it & 1;
        if (it + 1 < NK) load_tiles((it + 1) * BK);

#pragma unroll
        for (int kb = 0; kb < BK; kb += 8) {
            uint32_t af[2][4], bf[8][2];
#pragma unroll
            for (int mt = 0; mt < 2; mt++) {
                int r = wm + mt * 16 + grp;
                af[mt][0] = As[buf][kb + t4][r];
                af[mt][1] = As[buf][kb + t4][r + 8];
                af[mt][2] = As[buf][kb + t4 + 4][r];
                af[mt][3] = As[buf][kb + t4 + 4][r + 8];
            }
#pragma unroll
            for (int nt = 0; nt < 8; nt++) {
                int c = wn + nt * 8 + grp;
                bf[nt][0] = Bs[buf][kb + t4][c];
                bf[nt][1] = Bs[buf][kb + t4 + 4][c];
            }
#pragma unroll
            for (int mt = 0; mt < 2; mt++)
#pragma unroll
                for (int nt = 0; nt < 8; nt++)
                    mma_tf32(acc[mt][nt][0], acc[mt][nt][1],
                             acc[mt][nt][2], acc[mt][nt][3],
                             af[mt][0], af[mt][1], af[mt][2], af[mt][3],
                             bf[nt][0], bf[nt][1]);
        }

        if (it + 1 < NK) store_tiles(buf ^ 1);
        __syncthreads();
    }

#pragma unroll
    for (int mt = 0; mt < 2; mt++) {
        int row = m0 + wm + mt * 16 + grp;
#pragma unroll
        for (int nt = 0; nt < 8; nt++) {
            int col = n0 + wn + nt * 8 + 2 * t4;
            if (row < N_NODES) {
                float2 v01 = make_float2(acc[mt][nt][0], acc[mt][nt][1]);
                *reinterpret_cast<float2*>(&g_h[(long long)row * F1 + col]) = v01;
            }
            if (row + 8 < N_NODES) {
                float2 v23 = make_float2(acc[mt][nt][2], acc[mt][nt][3]);
                *reinterpret_cast<float2*>(&g_h[(long long)(row + 8) * F1 + col]) = v23;
            }
        }
    }
}

// ---------------- tiled fp32 GEMM (layers 2/3): g_h = op(g_agg) @ B ---------
template <bool RELU_A>
__global__ __launch_bounds__(256)
void k_gemm(const float* __restrict__ B, int M, int K, int Nc) {
    const float* A = g_agg;
    float* C = g_h;

    const int BM = 128, BN = 64, BK = 8;
    __shared__ float As[BK][BM];
    __shared__ float Bs[BK][BN];

    int tid = threadIdx.x;
    int m0 = blockIdx.x * BM;
    int n0 = blockIdx.y * BN;

    int ty = tid >> 4;
    int tx = tid & 15;

    int arow = tid >> 1;
    int akc  = (tid & 1) * 4;

    float acc[8][4];
#pragma unroll
    for (int i = 0; i < 8; i++)
#pragma unroll
        for (int j = 0; j < 4; j++) acc[i][j] = 0.0f;

    for (int k0 = 0; k0 < K; k0 += BK) {
        {
            int gm = m0 + arow;
            float4 v = make_float4(0.f, 0.f, 0.f, 0.f);
            if (gm < M)
                v = *reinterpret_cast<const float4*>(
                        &A[(long long)gm * K + k0 + akc]);
            if (RELU_A) {
                v.x = fmaxf(v.x, 0.f); v.y = fmaxf(v.y, 0.f);
                v.z = fmaxf(v.z, 0.f); v.w = fmaxf(v.w, 0.f);
            }
            As[akc + 0][arow] = v.x;
            As[akc + 1][arow] = v.y;
            As[akc + 2][arow] = v.z;
            As[akc + 3][arow] = v.w;
        }
        if (tid < 128) {
            int br = tid >> 4;
            int bc2 = (tid & 15) * 4;
            float4 v = *reinterpret_cast<const float4*>(
                &B[(long long)(k0 + br) * Nc + n0 + bc2]);
            *reinterpret_cast<float4*>(&Bs[br][bc2]) = v;
        }
        __syncthreads();

#pragma unroll
        for (int k = 0; k < BK; k++) {
            float a[8];
#pragma unroll
            for (int i = 0; i < 8; i++) a[i] = As[k][ty * 8 + i];
            float4 bv = *reinterpret_cast<float4*>(&Bs[k][tx * 4]);
            float b[4] = {bv.x, bv.y, bv.z, bv.w};
#pragma unroll
            for (int i = 0; i < 8; i++)
#pragma unroll
                for (int j = 0; j < 4; j++) acc[i][j] += a[i] * b[j];
        }
        __syncthreads();
    }

#pragma unroll
    for (int i = 0; i < 8; i++) {
        int gm = m0 + ty * 8 + i;
        if (gm < M) {
            float4 o = make_float4(acc[i][0], acc[i][1], acc[i][2], acc[i][3]);
            *reinterpret_cast<float4*>(&C[(long long)gm * Nc + n0 + tx * 4]) = o;
        }
    }
}

// ---------------- CSR gather: agg[i] = bias + dis²·h[i] + Σ w·h[src] -------
// 256/F nodes per block; each thread owns one feature of one node.
// FINAL: fuse out = sigmoid(x3 @ Wl + bl) (F == 64 only).
template <int F, bool EXT_OUT, bool FINAL>
__global__ __launch_bounds__(256)
void k_gather(const float* __restrict__ bias, float* __restrict__ out_ext,
              const float* __restrict__ Wl, const float* __restrict__ bl,
              float* __restrict__ out01) {
    const int NPB = 256 / F;
    __shared__ float red[8];

    int node = blockIdx.x * NPB + threadIdx.x / F;
    int f    = threadIdx.x & (F - 1);
    if (node >= N_NODES) return;       // never taken: 50000 % NPB == 0

    float dis = g_dis[node];
    float acc = g_h[(long long)node * F + f] * dis * dis + bias[f];

    int beg = g_rowptr[node];
    int end = g_rowptr[node + 1];
    int j = beg;
    // 4-wide software pipeline for MLP
    for (; j + 4 <= end; j += 4) {
        int   s0 = g_csr_src[j],     s1 = g_csr_src[j + 1];
        int   s2 = g_csr_src[j + 2], s3 = g_csr_src[j + 3];
        float w0 = g_csr_w[j],       w1 = g_csr_w[j + 1];
        float w2 = g_csr_w[j + 2],   w3 = g_csr_w[j + 3];
        float h0 = g_h[(long long)s0 * F + f];
        float h1 = g_h[(long long)s1 * F + f];
        float h2 = g_h[(long long)s2 * F + f];
        float h3 = g_h[(long long)s3 * F + f];
        acc += w0 * h0 + w1 * h1 + w2 * h2 + w3 * h3;
    }
    for (; j < end; j++) {
        int s = g_csr_src[j];
        acc += g_csr_w[j] * g_h[(long long)s * F + f];
    }

    float* o = EXT_OUT ? out_ext : g_agg;
    o[(long long)node * F + f] = acc;

    if (FINAL) {
        // dot(x3_row, Wl) across the F=64 threads of this node (2 aligned warps)
        float p = acc * Wl[f];
#pragma unroll
        for (int off = 16; off > 0; off >>= 1)
            p += __shfl_down_sync(0xFFFFFFFFu, p, off);
        int warp = threadIdx.x >> 5;
        if ((threadIdx.x & 31) == 0) red[warp] = p;
        __syncthreads();
        if (f == 0) {
            float s = red[warp] + red[warp + 1] + bl[0];
            out01[node] = 1.0f / (1.0f + expf(-s));
        }
    }
}

// ---------------- launcher ---------------------------------------------------
extern "C" void kernel_launch(void* const* d_in, const int* in_sizes, int n_in,
                              void* d_out, int out_size) {
    const float* x    = (const float*)d_in[0];
    const int*   ei32 = (const int*)d_in[1];
    const float* W1 = (const float*)d_in[2];
    const float* b1 = (const float*)d_in[3];
    const float* W2 = (const float*)d_in[4];
    const float* b2 = (const float*)d_in[5];
    const float* W3 = (const float*)d_in[6];
    const float* b3 = (const float*)d_in[7];
    const float* Wl = (const float*)d_in[8];
    const float* bl = (const float*)d_in[9];

    float* out = (float*)d_out;          // [N] sigmoid output first
    float* x3  = out + N_NODES;          // [N, 64] second output region

    const int T = 256;
    dim3 blk(T);
    const int NBn = (N_NODES + T - 1) / T;   // 196
    const int NBe = (N_EDGES + T - 1) / T;

    // ---- CSR build (once per launch) ----
    k_probe<<<1, blk>>>(ei32);
    k_zero<<<NBn, blk>>>();
    k_deg_count<<<NBe, blk>>>(ei32);
    k_rsqrt<<<NBn, blk>>>();
    k_scan1<<<SCAN_NB, blk>>>();
    k_scan2<<<1, blk>>>();
    k_scan3<<<SCAN_NB, blk>>>();
    k_fill<<<NBe, blk>>>(ei32);

    // ---- layer 1: 3000 -> 256 (tf32 tensor-core GEMM) ----
    {
        dim3 grid(F1 / 128, (N_NODES + 127) / 128);
        k_gemm1_tf32<<<grid, blk>>>(x, W1);
        k_gather<F1, false, false><<<N_NODES / (256 / F1), blk>>>(
            b1, nullptr, nullptr, nullptr, nullptr);
    }

    // ---- layer 2: 256 -> 128 (ReLU fused into A-load) ----
    {
        dim3 grid((N_NODES + 127) / 128, F2 / 64);
        k_gemm<true><<<grid, blk>>>(W2, N_NODES, F1, F2);
        k_gather<F2, false, false><<<N_NODES / (256 / F2), blk>>>(
            b2, nullptr, nullptr, nullptr, nullptr);
    }

    // ---- layer 3: 128 -> 64; gather writes x3 AND fused sigmoid head ----
    {
        dim3 grid((N_NODES + 127) / 128, F3 / 64);
        k_gemm<false><<<grid, blk>>>(W3, N_NODES, F2, F3);
        k_gather<F3, true, true><<<N_NODES / (256 / F3), blk>>>(
            b3, x3, Wl, bl, out);
    }
}

// round 7
// speedup vs baseline: 4.3104x; 1.3035x over previous
#include <cuda_runtime.h>
#include <cstdint>

#define N_NODES 50000
#define N_EDGES 1600000
#define D_IN    3000
#define F1      256
#define F2      128
#define F3      64
#define SCAN_NB ((N_NODES + 255) / 256)   // 196

// ---------------- scratch (static device arrays; alloc-free rule) ----------
__device__ float g_h[(size_t)N_NODES * F1];    // GEMM output h (per layer)
__device__ float g_agg[(size_t)N_NODES * F1];  // aggregation buffer
__device__ float g_dis[N_NODES];               // rsqrt(deg)
__device__ int   g_indeg[N_NODES];
__device__ int   g_rowptr[N_NODES + 1];
__device__ int   g_cursor[N_NODES];
__device__ int   g_csr_src[N_EDGES];
__device__ float g_csr_w[N_EDGES];
__device__ int   g_blocksum[256];
__device__ int   g_is64;

// ---------------- dtype probe ------------------------------------------------
__global__ void k_probe(const int* __restrict__ ei32) {
    __shared__ int bad;
    if (threadIdx.x == 0) bad = 0;
    __syncthreads();
    for (int i = threadIdx.x; i < 2048; i += blockDim.x) {
        if (ei32[2 * i + 1] != 0) atomicOr(&bad, 1);
    }
    __syncthreads();
    if (threadIdx.x == 0) g_is64 = bad ? 0 : 1;
}

__device__ __forceinline__ int load_idx(const int* __restrict__ ei32, long long pos) {
    int v = g_is64 ? ei32[2 * pos] : ei32[pos];
    v = v < 0 ? 0 : (v >= N_NODES ? N_NODES - 1 : v);
    return v;
}

// ---------------- degree / CSR build ----------------------------------------
__global__ void k_zero() {
    int i = blockIdx.x * blockDim.x + threadIdx.x;
    if (i < N_NODES) { g_indeg[i] = 0; g_cursor[i] = 0; }
}

__global__ void k_deg_count(const int* __restrict__ ei32) {
    int e = blockIdx.x * blockDim.x + threadIdx.x;
    if (e < N_EDGES) {
        int d = load_idx(ei32, (long long)N_EDGES + e);
        atomicAdd(&g_indeg[d], 1);
    }
}

__global__ void k_rsqrt() {
    int i = blockIdx.x * blockDim.x + threadIdx.x;
    if (i < N_NODES) g_dis[i] = rsqrtf((float)g_indeg[i] + 1.0f);
}

__global__ void k_scan1() {
    __shared__ int s[256];
    int b = blockIdx.x, t = threadIdx.x;
    int i = b * 256 + t;
    int v = (i < N_NODES) ? g_indeg[i] : 0;
    s[t] = v;
    __syncthreads();
#pragma unroll
    for (int off = 1; off < 256; off <<= 1) {
        int add = (t >= off) ? s[t - off] : 0;
        __syncthreads();
        s[t] += add;
        __syncthreads();
    }
    if (i < N_NODES) g_rowptr[i + 1] = s[t];
    if (t == 255) g_blocksum[b] = s[255];
}

__global__ void k_scan2() {
    __shared__ int s[256];
    int t = threadIdx.x;
    int v = (t < SCAN_NB) ? g_blocksum[t] : 0;
    s[t] = v;
    __syncthreads();
#pragma unroll
    for (int off = 1; off < 256; off <<= 1) {
        int add = (t >= off) ? s[t - off] : 0;
        __syncthreads();
        s[t] += add;
        __syncthreads();
    }
    g_blocksum[t] = s[t] - v;   // exclusive
}

__global__ void k_scan3() {
    int i = blockIdx.x * blockDim.x + threadIdx.x;
    if (i < N_NODES) g_rowptr[i + 1] += g_blocksum[blockIdx.x];
    if (i == 0) g_rowptr[0] = 0;
}

__global__ void k_fill(const int* __restrict__ ei32) {
    int e = blockIdx.x * blockDim.x + threadIdx.x;
    if (e < N_EDGES) {
        int s = load_idx(ei32, e);
        int d = load_idx(ei32, (long long)N_EDGES + e);
        int pos = g_rowptr[d] + atomicAdd(&g_cursor[d], 1);
        g_csr_src[pos] = s;
        g_csr_w[pos]   = g_dis[s] * g_dis[d];
    }
}

// ---------------- format helpers ---------------------------------------------
__device__ __forceinline__ uint32_t f2tf32(float x) {
    uint32_t r;
    asm("cvt.rna.tf32.f32 %0, %1;" : "=r"(r) : "f"(x));
    return r;
}

// pack: low 16 bits = lo (even k), high 16 bits = hi (odd k)
__device__ __forceinline__ uint32_t pack_bf16(float lo, float hi) {
    uint32_t r;
    asm("cvt.rn.bf16x2.f32 %0, %1, %2;" : "=r"(r) : "f"(hi), "f"(lo));
    return r;
}

__device__ __forceinline__ void mma_tf32(float& c0, float& c1, float& c2, float& c3,
                                         uint32_t a0, uint32_t a1, uint32_t a2, uint32_t a3,
                                         uint32_t b0, uint32_t b1) {
    asm volatile(
        "mma.sync.aligned.m16n8k8.row.col.f32.tf32.tf32.f32 "
        "{%0,%1,%2,%3}, {%4,%5,%6,%7}, {%8,%9}, {%0,%1,%2,%3};"
        : "+f"(c0), "+f"(c1), "+f"(c2), "+f"(c3)
        : "r"(a0), "r"(a1), "r"(a2), "r"(a3), "r"(b0), "r"(b1));
}

__device__ __forceinline__ void mma_bf16(float& c0, float& c1, float& c2, float& c3,
                                         uint32_t a0, uint32_t a1, uint32_t a2, uint32_t a3,
                                         uint32_t b0, uint32_t b1) {
    asm volatile(
        "mma.sync.aligned.m16n8k16.row.col.f32.bf16.bf16.f32 "
        "{%0,%1,%2,%3}, {%4,%5,%6,%7}, {%8,%9}, {%0,%1,%2,%3};"
        : "+f"(c0), "+f"(c1), "+f"(c2), "+f"(c3)
        : "r"(a0), "r"(a1), "r"(a2), "r"(a3), "r"(b0), "r"(b1));
}

// ---------------- GEMM1: g_h[M,256] = x[M,3000] @ W1[3000,256] (bf16 MMA) ---
// BM=128, BN=128, BK=16; 8 warps (4M x 2N), warp tile 32x64, m16n8k16.
// SMEM holds bf16x2 pairs along k: As32[kk][m], Bs32[kk][n], kk = k/2.
// Double-buffered, register prefetch, 1 sync/iter.
__global__ __launch_bounds__(256)
void k_gemm1_bf16(const float* __restrict__ A, const float* __restrict__ B) {
    const int BM = 128, LDS_S = 132;
    __shared__ uint32_t As32[2][8][LDS_S];   // [buf][kk][m]
    __shared__ uint32_t Bs32[2][8][LDS_S];   // [buf][kk][n]

    const int tid  = threadIdx.x;
    const int m0   = blockIdx.y * BM;
    const int n0   = blockIdx.x * 128;
    const int warp = tid >> 5, lane = tid & 31;
    const int wm = (warp & 3) * 32;
    const int wn = (warp >> 2) * 64;
    const int grp = lane >> 2, t4 = lane & 3;

    float acc[2][8][4];
#pragma unroll
    for (int i = 0; i < 2; i++)
#pragma unroll
        for (int j = 0; j < 8; j++)
#pragma unroll
            for (int q = 0; q < 4; q++) acc[i][j][q] = 0.0f;

    // A-load: 512 float4 per tile (128 rows x 16k), 2 per thread
    int arow[2], akc[2];
    const float* aptr[2];
    bool aval[2];
#pragma unroll
    for (int i = 0; i < 2; i++) {
        int f = tid + i * 256;
        arow[i] = f >> 2;
        akc[i]  = (f & 3) * 4;
        int gm  = m0 + arow[i];
        aval[i] = (gm < N_NODES);
        aptr[i] = A + (long long)(aval[i] ? gm : 0) * D_IN;
    }
    // B-load: kk = tid>>5 (0..7), n = (tid&31)*4; loads rows 2kk, 2kk+1
    const int bkk = tid >> 5;
    const int bn  = (tid & 31) * 4;

    const int NK = (D_IN + 15) / 16;   // 188 (last partial, zero-filled)

    float4 ra[2], rb0, rb1;
    auto load_tiles = [&](int k0) {
#pragma unroll
        for (int i = 0; i < 2; i++) {
            ra[i] = make_float4(0.f, 0.f, 0.f, 0.f);
            if (aval[i] && (k0 + akc[i] < D_IN))
                ra[i] = *reinterpret_cast<const float4*>(aptr[i] + k0 + akc[i]);
        }
        rb0 = make_float4(0.f, 0.f, 0.f, 0.f);
        rb1 = make_float4(0.f, 0.f, 0.f, 0.f);
        int kr = k0 + 2 * bkk;
        if (kr < D_IN) {    // D_IN even -> kr+1 valid too
            rb0 = *reinterpret_cast<const float4*>(&B[(long long)kr * F1 + n0 + bn]);
            rb1 = *reinterpret_cast<const float4*>(&B[(long long)(kr + 1) * F1 + n0 + bn]);
        }
    };
    auto store_tiles = [&](int buf) {
#pragma unroll
        for (int i = 0; i < 2; i++) {
            int kk = akc[i] >> 1;   // akc in {0,4,8,12} -> kk in {0,2,4,6}
            As32[buf][kk + 0][arow[i]] = pack_bf16(ra[i].x, ra[i].y);
            As32[buf][kk + 1][arow[i]] = pack_bf16(ra[i].z, ra[i].w);
        }
        uint4 u;
        u.x = pack_bf16(rb0.x, rb1.x);
        u.y = pack_bf16(rb0.y, rb1.y);
        u.z = pack_bf16(rb0.z, rb1.z);
        u.w = pack_bf16(rb0.w, rb1.w);
        *reinterpret_cast<uint4*>(&Bs32[buf][bkk][bn]) = u;
    };

    load_tiles(0);
    store_tiles(0);
    __syncthreads();

    for (int it = 0; it < NK; it++) {
        int buf = it & 1;
        if (it + 1 < NK) load_tiles((it + 1) * 16);

        uint32_t af[2][4], bf[8][2];
#pragma unroll
        for (int mt = 0; mt < 2; mt++) {
            int r = wm + mt * 16 + grp;
            af[mt][0] = As32[buf][t4][r];
            af[mt][1] = As32[buf][t4][r + 8];
            af[mt][2] = As32[buf][t4 + 4][r];
            af[mt][3] = As32[buf][t4 + 4][r + 8];
        }
#pragma unroll
        for (int nt = 0; nt < 8; nt++) {
            int c = wn + nt * 8 + grp;
            bf[nt][0] = Bs32[buf][t4][c];
            bf[nt][1] = Bs32[buf][t4 + 4][c];
        }
#pragma unroll
        for (int mt = 0; mt < 2; mt++)
#pragma unroll
            for (int nt = 0; nt < 8; nt++)
                mma_bf16(acc[mt][nt][0], acc[mt][nt][1],
                         acc[mt][nt][2], acc[mt][nt][3],
                         af[mt][0], af[mt][1], af[mt][2], af[mt][3],
                         bf[nt][0], bf[nt][1]);

        if (it + 1 < NK) store_tiles(buf ^ 1);
        __syncthreads();
    }

#pragma unroll
    for (int mt = 0; mt < 2; mt++) {
        int row = m0 + wm + mt * 16 + grp;
#pragma unroll
        for (int nt = 0; nt < 8; nt++) {
            int col = n0 + wn + nt * 8 + 2 * t4;
            if (row < N_NODES) {
                float2 v01 = make_float2(acc[mt][nt][0], acc[mt][nt][1]);
                *reinterpret_cast<float2*>(&g_h[(long long)row * F1 + col]) = v01;
            }
            if (row + 8 < N_NODES) {
                float2 v23 = make_float2(acc[mt][nt][2], acc[mt][nt][3]);
                *reinterpret_cast<float2*>(&g_h[(long long)(row + 8) * F1 + col]) = v23;
            }
        }
    }
}

// ---------------- GEMM 2/3: g_h[M,BN] = op(g_agg)[M,KD] @ B[KD,BN] (tf32) ---
// BM=128; BN = 128 (nt=8) or 64 (nt=4); warp layout 4M x 2N, warp tile 32 x BN/2.
// Single-buffered (small K; not on the critical path like GEMM1).
template <int KD, int BN, bool RELU_A>
__global__ __launch_bounds__(256)
void k_gemm23(const float* __restrict__ B) {
    const int NT = BN / 16;            // n-tiles per warp
    __shared__ uint32_t As[16][132];
    __shared__ uint32_t Bs[16][BN + 4];

    const int tid  = threadIdx.x;
    const int m0   = blockIdx.x * 128;
    const int n0   = blockIdx.y * BN;
    const int warp = tid >> 5, lane = tid & 31;
    const int wm = (warp & 3) * 32;
    const int wn = (warp >> 2) * (BN / 2);
    const int grp = lane >> 2, t4 = lane & 3;

    float acc[2][NT][4];
#pragma unroll
    for (int i = 0; i < 2; i++)
#pragma unroll
        for (int j = 0; j < NT; j++)
#pragma unroll
            for (int q = 0; q < 4; q++) acc[i][j][q] = 0.0f;

    // A-load: 128 rows x 16 k = 512 float4, 2 per thread
    int arow[2], akc[2];
#pragma unroll
    for (int i = 0; i < 2; i++) {
        int f = tid + i * 256;
        arow[i] = f >> 2;
        akc[i]  = (f & 3) * 4;
    }

    for (int k0 = 0; k0 < KD; k0 += 16) {
#pragma unroll
        for (int i = 0; i < 2; i++) {
            int gm = m0 + arow[i];
            float4 v = make_float4(0.f, 0.f, 0.f, 0.f);
            if (gm < N_NODES)
                v = *reinterpret_cast<const float4*>(
                        &g_agg[(long long)gm * KD + k0 + akc[i]]);
            if (RELU_A) {
                v.x = fmaxf(v.x, 0.f); v.y = fmaxf(v.y, 0.f);
                v.z = fmaxf(v.z, 0.f); v.w = fmaxf(v.w, 0.f);
            }
            As[akc[i] + 0][arow[i]] = f2tf32(v.x);
            As[akc[i] + 1][arow[i]] = f2tf32(v.y);
            As[akc[i] + 2][arow[i]] = f2tf32(v.z);
            As[akc[i] + 3][arow[i]] = f2tf32(v.w);
        }
        // B-load: 16 rows x BN cols = 4*BN float4s
        {
            const int NF = 4 * BN;           // 512 (BN=128) or 256 (BN=64)
#pragma unroll
            for (int i = 0; i < NF / 256; i++) {
                int f = tid + i * 256;
                int br = f / (BN / 4);
                int bc = (f % (BN / 4)) * 4;
                float4 v = *reinterpret_cast<const float4*>(
                    &B[(long long)(k0 + br) * BN + n0 + bc]);
                Bs[br][bc + 0] = f2tf32(v.x);
                Bs[br][bc + 1] = f2tf32(v.y);
                Bs[br][bc + 2] = f2tf32(v.z);
                Bs[br][bc + 3] = f2tf32(v.w);
            }
        }
        __syncthreads();

#pragma unroll
        for (int kb = 0; kb < 16; kb += 8) {
            uint32_t af[2][4], bfr[NT][2];
#pragma unroll
            for (int mt = 0; mt < 2; mt++) {
                int r = wm + mt * 16 + grp;
                af[mt][0] = As[kb + t4][r];
                af[mt][1] = As[kb + t4][r + 8];
                af[mt][2] = As[kb + t4 + 4][r];
                af[mt][3] = As[kb + t4 + 4][r + 8];
            }
#pragma unroll
            for (int nt = 0; nt < NT; nt++) {
                int c = wn + nt * 8 + grp;
                bfr[nt][0] = Bs[kb + t4][c];
                bfr[nt][1] = Bs[kb + t4 + 4][c];
            }
#pragma unroll
            for (int mt = 0; mt < 2; mt++)
#pragma unroll
                for (int nt = 0; nt < NT; nt++)
                    mma_tf32(acc[mt][nt][0], acc[mt][nt][1],
                             acc[mt][nt][2], acc[mt][nt][3],
                             af[mt][0], af[mt][1], af[mt][2], af[mt][3],
                             bfr[nt][0], bfr[nt][1]);
        }
        __syncthreads();
    }

#pragma unroll
    for (int mt = 0; mt < 2; mt++) {
        int row = m0 + wm + mt * 16 + grp;
#pragma unroll
        for (int nt = 0; nt < NT; nt++) {
            int col = n0 + wn + nt * 8 + 2 * t4;
            if (row < N_NODES) {
                float2 v01 = make_float2(acc[mt][nt][0], acc[mt][nt][1]);
                *reinterpret_cast<float2*>(&g_h[(long long)row * BN + col]) = v01;
            }
            if (row + 8 < N_NODES) {
                float2 v23 = make_float2(acc[mt][nt][2], acc[mt][nt][3]);
                *reinterpret_cast<float2*>(&g_h[(long long)(row + 8) * BN + col]) = v23;
            }
        }
    }
}

// ---------------- CSR gather: agg[i] = bias + dis²·h[i] + Σ w·h[src] -------
template <int F, bool EXT_OUT, bool FINAL>
__global__ __launch_bounds__(256)
void k_gather(const float* __restrict__ bias, float* __restrict__ out_ext,
              const float* __restrict__ Wl, const float* __restrict__ bl,
              float* __restrict__ out01) {
    const int NPB = 256 / F;
    __shared__ float red[8];

    int node = blockIdx.x * NPB + threadIdx.x / F;
    int f    = threadIdx.x & (F - 1);
    if (node >= N_NODES) return;

    float dis = g_dis[node];
    float acc = g_h[(long long)node * F + f] * dis * dis + bias[f];

    int beg = g_rowptr[node];
    int end = g_rowptr[node + 1];
    int j = beg;
    for (; j + 4 <= end; j += 4) {
        int   s0 = g_csr_src[j],     s1 = g_csr_src[j + 1];
        int   s2 = g_csr_src[j + 2], s3 = g_csr_src[j + 3];
        float w0 = g_csr_w[j],       w1 = g_csr_w[j + 1];
        float w2 = g_csr_w[j + 2],   w3 = g_csr_w[j + 3];
        float h0 = g_h[(long long)s0 * F + f];
        float h1 = g_h[(long long)s1 * F + f];
        float h2 = g_h[(long long)s2 * F + f];
        float h3 = g_h[(long long)s3 * F + f];
        acc += w0 * h0 + w1 * h1 + w2 * h2 + w3 * h3;
    }
    for (; j < end; j++) {
        int s = g_csr_src[j];
        acc += g_csr_w[j] * g_h[(long long)s * F + f];
    }

    float* o = EXT_OUT ? out_ext : g_agg;
    o[(long long)node * F + f] = acc;

    if (FINAL) {
        float p = acc * Wl[f];
#pragma unroll
        for (int off = 16; off > 0; off >>= 1)
            p += __shfl_down_sync(0xFFFFFFFFu, p, off);
        int warp = threadIdx.x >> 5;
        if ((threadIdx.x & 31) == 0) red[warp] = p;
        __syncthreads();
        if (f == 0) {
            float s = red[warp] + red[warp + 1] + bl[0];
            out01[node] = 1.0f / (1.0f + expf(-s));
        }
    }
}

// ---------------- launcher ---------------------------------------------------
extern "C" void kernel_launch(void* const* d_in, const int* in_sizes, int n_in,
                              void* d_out, int out_size) {
    const float* x    = (const float*)d_in[0];
    const int*   ei32 = (const int*)d_in[1];
    const float* W1 = (const float*)d_in[2];
    const float* b1 = (const float*)d_in[3];
    const float* W2 = (const float*)d_in[4];
    const float* b2 = (const float*)d_in[5];
    const float* W3 = (const float*)d_in[6];
    const float* b3 = (const float*)d_in[7];
    const float* Wl = (const float*)d_in[8];
    const float* bl = (const float*)d_in[9];

    float* out = (float*)d_out;          // [N] sigmoid output first
    float* x3  = out + N_NODES;          // [N, 64] second output region

    const int T = 256;
    dim3 blk(T);
    const int NBn = (N_NODES + T - 1) / T;
    const int NBe = (N_EDGES + T - 1) / T;

    // ---- CSR build ----
    k_probe<<<1, blk>>>(ei32);
    k_zero<<<NBn, blk>>>();
    k_deg_count<<<NBe, blk>>>(ei32);
    k_rsqrt<<<NBn, blk>>>();
    k_scan1<<<SCAN_NB, blk>>>();
    k_scan2<<<1, blk>>>();
    k_scan3<<<SCAN_NB, blk>>>();
    k_fill<<<NBe, blk>>>(ei32);

    // ---- layer 1: 3000 -> 256 (bf16 tensor-core GEMM) ----
    {
        dim3 grid(F1 / 128, (N_NODES + 127) / 128);
        k_gemm1_bf16<<<grid, blk>>>(x, W1);
        k_gather<F1, false, false><<<N_NODES / (256 / F1), blk>>>(
            b1, nullptr, nullptr, nullptr, nullptr);
    }

    // ---- layer 2: 256 -> 128 (tf32 MMA, ReLU fused into A-load) ----
    {
        dim3 grid((N_NODES + 127) / 128, 1);
        k_gemm23<F1, F2, true><<<grid, blk>>>(W2);
        k_gather<F2, false, false><<<N_NODES / (256 / F2), blk>>>(
            b2, nullptr, nullptr, nullptr, nullptr);
    }

    // ---- layer 3: 128 -> 64 (tf32 MMA); gather writes x3 + fused head ----
    {
        dim3 grid((N_NODES + 127) / 128, 1);
        k_gemm23<F2, F3, false><<<grid, blk>>>(W3);
        k_gather<F3, true, true><<<N_NODES / (256 / F3), blk>>>(
            b3, x3, Wl, bl, out);
    }
}

// round 9
// speedup vs baseline: 4.4987x; 1.0437x over previous
#include <cuda_runtime.h>
#include <cstdint>

#define N_NODES 50000
#define N_EDGES 1600000
#define D_IN    3000
#define F1      256
#define F2      128
#define F3      64
#define SCAN_NB ((N_NODES + 255) / 256)   // 196

// ---------------- scratch (static device arrays; alloc-free rule) ----------
__device__ float g_h[(size_t)N_NODES * F1];
__device__ float g_agg[(size_t)N_NODES * F1];
__device__ float g_dis[N_NODES];
__device__ int   g_indeg[N_NODES];
__device__ int   g_rowptr[N_NODES + 1];
__device__ int   g_cursor[N_NODES];
__device__ int   g_csr_src[N_EDGES];
__device__ float g_csr_w[N_EDGES];
__device__ int   g_blocksum[256];
__device__ int   g_is64;

// ---------------- host-side streams (created at program init, pre-capture) --
namespace {
struct HxStreams {
    cudaStream_t s2 = nullptr;
    cudaEvent_t  e1 = nullptr, e2 = nullptr;
    bool ok = false;
    HxStreams() {
        ok = (cudaStreamCreateWithFlags(&s2, cudaStreamNonBlocking) == cudaSuccess) &&
             (cudaEventCreateWithFlags(&e1, cudaEventDisableTiming) == cudaSuccess) &&
             (cudaEventCreateWithFlags(&e2, cudaEventDisableTiming) == cudaSuccess);
    }
};
HxStreams g_hx;   // constructed before main(); never destroyed (process-lifetime)
}

// ---------------- init: zero counters + dtype probe (block 0) ---------------
// int64 little-endian indices in [0,50000) => every odd 32-bit word is 0.
__global__ void k_init(const int* __restrict__ ei32) {
    int i = blockIdx.x * blockDim.x + threadIdx.x;
    if (i < N_NODES) { g_indeg[i] = 0; g_cursor[i] = 0; }
    if (blockIdx.x == 0) {
        __shared__ int bad;
        if (threadIdx.x == 0) bad = 0;
        __syncthreads();
        for (int j = threadIdx.x; j < 2048; j += blockDim.x)
            if (ei32[2 * j + 1] != 0) atomicOr(&bad, 1);
        __syncthreads();
        if (threadIdx.x == 0) g_is64 = bad ? 0 : 1;
    }
}

__device__ __forceinline__ int load_idx(const int* __restrict__ ei32, long long pos) {
    int v = g_is64 ? ei32[2 * pos] : ei32[pos];
    v = v < 0 ? 0 : (v >= N_NODES ? N_NODES - 1 : v);
    return v;
}

// ---------------- degree / CSR build ----------------------------------------
__global__ void k_deg_count(const int* __restrict__ ei32) {
    int e = blockIdx.x * blockDim.x + threadIdx.x;
    if (e < N_EDGES) {
        int d = load_idx(ei32, (long long)N_EDGES + e);
        atomicAdd(&g_indeg[d], 1);
    }
}

__global__ void k_rsqrt() {
    int i = blockIdx.x * blockDim.x + threadIdx.x;
    if (i < N_NODES) g_dis[i] = rsqrtf((float)g_indeg[i] + 1.0f);
}

__global__ void k_scan1() {
    __shared__ int s[256];
    int b = blockIdx.x, t = threadIdx.x;
    int i = b * 256 + t;
    int v = (i < N_NODES) ? g_indeg[i] : 0;
    s[t] = v;
    __syncthreads();
#pragma unroll
    for (int off = 1; off < 256; off <<= 1) {
        int add = (t >= off) ? s[t - off] : 0;
        __syncthreads();
        s[t] += add;
        __syncthreads();
    }
    if (i < N_NODES) g_rowptr[i + 1] = s[t];
    if (t == 255) g_blocksum[b] = s[255];
}

__global__ void k_scan2() {
    __shared__ int s[256];
    int t = threadIdx.x;
    int v = (t < SCAN_NB) ? g_blocksum[t] : 0;
    s[t] = v;
    __syncthreads();
#pragma unroll
    for (int off = 1; off < 256; off <<= 1) {
        int add = (t >= off) ? s[t - off] : 0;
        __syncthreads();
        s[t] += add;
        __syncthreads();
    }
    g_blocksum[t] = s[t] - v;   // exclusive
}

__global__ void k_scan3() {
    int i = blockIdx.x * blockDim.x + threadIdx.x;
    if (i < N_NODES) g_rowptr[i + 1] += g_blocksum[blockIdx.x];
    if (i == 0) g_rowptr[0] = 0;
}

__global__ void k_fill(const int* __restrict__ ei32) {
    int e = blockIdx.x * blockDim.x + threadIdx.x;
    if (e < N_EDGES) {
        int s = load_idx(ei32, e);
        int d = load_idx(ei32, (long long)N_EDGES + e);
        int pos = g_rowptr[d] + atomicAdd(&g_cursor[d], 1);
        g_csr_src[pos] = s;
        g_csr_w[pos]   = g_dis[s] * g_dis[d];
    }
}

// ---------------- format helpers ---------------------------------------------
__device__ __forceinline__ uint32_t f2tf32(float x) {
    uint32_t r;
    asm("cvt.rna.tf32.f32 %0, %1;" : "=r"(r) : "f"(x));
    return r;
}

__device__ __forceinline__ uint32_t pack_bf16(float lo, float hi) {
    uint32_t r;
    asm("cvt.rn.bf16x2.f32 %0, %1, %2;" : "=r"(r) : "f"(hi), "f"(lo));
    return r;
}

__device__ __forceinline__ void mma_tf32(float& c0, float& c1, float& c2, float& c3,
                                         uint32_t a0, uint32_t a1, uint32_t a2, uint32_t a3,
                                         uint32_t b0, uint32_t b1) {
    asm volatile(
        "mma.sync.aligned.m16n8k8.row.col.f32.tf32.tf32.f32 "
        "{%0,%1,%2,%3}, {%4,%5,%6,%7}, {%8,%9}, {%0,%1,%2,%3};"
        : "+f"(c0), "+f"(c1), "+f"(c2), "+f"(c3)
        : "r"(a0), "r"(a1), "r"(a2), "r"(a3), "r"(b0), "r"(b1));
}

__device__ __forceinline__ void mma_bf16(float& c0, float& c1, float& c2, float& c3,
                                         uint32_t a0, uint32_t a1, uint32_t a2, uint32_t a3,
                                         uint32_t b0, uint32_t b1) {
    asm volatile(
        "mma.sync.aligned.m16n8k16.row.col.f32.bf16.bf16.f32 "
        "{%0,%1,%2,%3}, {%4,%5,%6,%7}, {%8,%9}, {%0,%1,%2,%3};"
        : "+f"(c0), "+f"(c1), "+f"(c2), "+f"(c3)
        : "r"(a0), "r"(a1), "r"(a2), "r"(a3), "r"(b0), "r"(b1));
}

// ---------------- GEMM1: g_h[M,256] = x[M,3000] @ W1[3000,256] (bf16 MMA) ---
// BM=128, BN=128, BK=16; 8 warps (4M x 2N), warp tile 32x64, m16n8k16.
// Double-buffered, register prefetch, 1 sync/iter.
__global__ __launch_bounds__(256)
void k_gemm1_bf16(const float* __restrict__ A, const float* __restrict__ B) {
    const int BM = 128, LDS_S = 132;
    __shared__ uint32_t As32[2][8][LDS_S];   // [buf][kk][m]
    __shared__ uint32_t Bs32[2][8][LDS_S];   // [buf][kk][n]

    const int tid  = threadIdx.x;
    const int m0   = blockIdx.y * BM;
    const int n0   = blockIdx.x * 128;
    const int warp = tid >> 5, lane = tid & 31;
    const int wm = (warp & 3) * 32;
    const int wn = (warp >> 2) * 64;
    const int grp = lane >> 2, t4 = lane & 3;

    float acc[2][8][4];
#pragma unroll
    for (int i = 0; i < 2; i++)
#pragma unroll
        for (int j = 0; j < 8; j++)
#pragma unroll
            for (int q = 0; q < 4; q++) acc[i][j][q] = 0.0f;

    int arow[2], akc[2];
    const float* aptr[2];
    bool aval[2];
#pragma unroll
    for (int i = 0; i < 2; i++) {
        int f = tid + i * 256;
        arow[i] = f >> 2;
        akc[i]  = (f & 3) * 4;
        int gm  = m0 + arow[i];
        aval[i] = (gm < N_NODES);
        aptr[i] = A + (long long)(aval[i] ? gm : 0) * D_IN;
    }
    const int bkk = tid >> 5;
    const int bn  = (tid & 31) * 4;

    const int NK = (D_IN + 15) / 16;   // 188

    float4 ra[2], rb0, rb1;
    auto load_tiles = [&](int k0) {
#pragma unroll
        for (int i = 0; i < 2; i++) {
            ra[i] = make_float4(0.f, 0.f, 0.f, 0.f);
            if (aval[i] && (k0 + akc[i] < D_IN))
                ra[i] = *reinterpret_cast<const float4*>(aptr[i] + k0 + akc[i]);
        }
        rb0 = make_float4(0.f, 0.f, 0.f, 0.f);
        rb1 = make_float4(0.f, 0.f, 0.f, 0.f);
        int kr = k0 + 2 * bkk;
        if (kr < D_IN) {
            rb0 = *reinterpret_cast<const float4*>(&B[(long long)kr * F1 + n0 + bn]);
            rb1 = *reinterpret_cast<const float4*>(&B[(long long)(kr + 1) * F1 + n0 + bn]);
        }
    };
    auto store_tiles = [&](int buf) {
#pragma unroll
        for (int i = 0; i < 2; i++) {
            int kk = akc[i] >> 1;
            As32[buf][kk + 0][arow[i]] = pack_bf16(ra[i].x, ra[i].y);
            As32[buf][kk + 1][arow[i]] = pack_bf16(ra[i].z, ra[i].w);
        }
        uint4 u;
        u.x = pack_bf16(rb0.x, rb1.x);
        u.y = pack_bf16(rb0.y, rb1.y);
        u.z = pack_bf16(rb0.z, rb1.z);
        u.w = pack_bf16(rb0.w, rb1.w);
        *reinterpret_cast<uint4*>(&Bs32[buf][bkk][bn]) = u;
    };

    load_tiles(0);
    store_tiles(0);
    __syncthreads();

    for (int it = 0; it < NK; it++) {
        int buf = it & 1;
        if (it + 1 < NK) load_tiles((it + 1) * 16);

        uint32_t af[2][4], bf[8][2];
#pragma unroll
        for (int mt = 0; mt < 2; mt++) {
            int r = wm + mt * 16 + grp;
            af[mt][0] = As32[buf][t4][r];
            af[mt][1] = As32[buf][t4][r + 8];
            af[mt][2] = As32[buf][t4 + 4][r];
            af[mt][3] = As32[buf][t4 + 4][r + 8];
        }
#pragma unroll
        for (int nt = 0; nt < 8; nt++) {
            int c = wn + nt * 8 + grp;
            bf[nt][0] = Bs32[buf][t4][c];
            bf[nt][1] = Bs32[buf][t4 + 4][c];
        }
#pragma unroll
        for (int mt = 0; mt < 2; mt++)
#pragma unroll
            for (int nt = 0; nt < 8; nt++)
                mma_bf16(acc[mt][nt][0], acc[mt][nt][1],
                         acc[mt][nt][2], acc[mt][nt][3],
                         af[mt][0], af[mt][1], af[mt][2], af[mt][3],
                         bf[nt][0], bf[nt][1]);

        if (it + 1 < NK) store_tiles(buf ^ 1);
        __syncthreads();
    }

#pragma unroll
    for (int mt = 0; mt < 2; mt++) {
        int row = m0 + wm + mt * 16 + grp;
#pragma unroll
        for (int nt = 0; nt < 8; nt++) {
            int col = n0 + wn + nt * 8 + 2 * t4;
            if (row < N_NODES) {
                float2 v01 = make_float2(acc[mt][nt][0], acc[mt][nt][1]);
                *reinterpret_cast<float2*>(&g_h[(long long)row * F1 + col]) = v01;
            }
            if (row + 8 < N_NODES) {
                float2 v23 = make_float2(acc[mt][nt][2], acc[mt][nt][3]);
                *reinterpret_cast<float2*>(&g_h[(long long)(row + 8) * F1 + col]) = v23;
            }
        }
    }
}

// ---------------- GEMM 2/3: g_h[M,BN] = op(g_agg)[M,KD] @ B[KD,BN] (tf32) ---
template <int KD, int BN, bool RELU_A>
__global__ __launch_bounds__(256)
void k_gemm23(const float* __restrict__ B) {
    const int NT = BN / 16;
    __shared__ uint32_t As[16][132];
    __shared__ uint32_t Bs[16][BN + 4];

    const int tid  = threadIdx.x;
    const int m0   = blockIdx.x * 128;
    const int n0   = blockIdx.y * BN;
    const int warp = tid >> 5, lane = tid & 31;
    const int wm = (warp & 3) * 32;
    const int wn = (warp >> 2) * (BN / 2);
    const int grp = lane >> 2, t4 = lane & 3;

    float acc[2][NT][4];
#pragma unroll
    for (int i = 0; i < 2; i++)
#pragma unroll
        for (int j = 0; j < NT; j++)
#pragma unroll
            for (int q = 0; q < 4; q++) acc[i][j][q] = 0.0f;

    int arow[2], akc[2];
#pragma unroll
    for (int i = 0; i < 2; i++) {
        int f = tid + i * 256;
        arow[i] = f >> 2;
        akc[i]  = (f & 3) * 4;
    }

    for (int k0 = 0; k0 < KD; k0 += 16) {
#pragma unroll
        for (int i = 0; i < 2; i++) {
            int gm = m0 + arow[i];
            float4 v = make_float4(0.f, 0.f, 0.f, 0.f);
            if (gm < N_NODES)
                v = *reinterpret_cast<const float4*>(
                        &g_agg[(long long)gm * KD + k0 + akc[i]]);
            if (RELU_A) {
                v.x = fmaxf(v.x, 0.f); v.y = fmaxf(v.y, 0.f);
                v.z = fmaxf(v.z, 0.f); v.w = fmaxf(v.w, 0.f);
            }
            As[akc[i] + 0][arow[i]] = f2tf32(v.x);
            As[akc[i] + 1][arow[i]] = f2tf32(v.y);
            As[akc[i] + 2][arow[i]] = f2tf32(v.z);
            As[akc[i] + 3][arow[i]] = f2tf32(v.w);
        }
        {
            const int NF = 4 * BN;
#pragma unroll
            for (int i = 0; i < NF / 256; i++) {
                int f = tid + i * 256;
                int br = f / (BN / 4);
                int bc = (f % (BN / 4)) * 4;
                float4 v = *reinterpret_cast<const float4*>(
                    &B[(long long)(k0 + br) * BN + n0 + bc]);
                Bs[br][bc + 0] = f2tf32(v.x);
                Bs[br][bc + 1] = f2tf32(v.y);
                Bs[br][bc + 2] = f2tf32(v.z);
                Bs[br][bc + 3] = f2tf32(v.w);
            }
        }
        __syncthreads();

#pragma unroll
        for (int kb = 0; kb < 16; kb += 8) {
            uint32_t af[2][4], bfr[NT][2];
#pragma unroll
            for (int mt = 0; mt < 2; mt++) {
                int r = wm + mt * 16 + grp;
                af[mt][0] = As[kb + t4][r];
                af[mt][1] = As[kb + t4][r + 8];
                af[mt][2] = As[kb + t4 + 4][r];
                af[mt][3] = As[kb + t4 + 4][r + 8];
            }
#pragma unroll
            for (int nt = 0; nt < NT; nt++) {
                int c = wn + nt * 8 + grp;
                bfr[nt][0] = Bs[kb + t4][c];
                bfr[nt][1] = Bs[kb + t4 + 4][c];
            }
#pragma unroll
            for (int mt = 0; mt < 2; mt++)
#pragma unroll
                for (int nt = 0; nt < NT; nt++)
                    mma_tf32(acc[mt][nt][0], acc[mt][nt][1],
                             acc[mt][nt][2], acc[mt][nt][3],
                             af[mt][0], af[mt][1], af[mt][2], af[mt][3],
                             bfr[nt][0], bfr[nt][1]);
        }
        __syncthreads();
    }

#pragma unroll
    for (int mt = 0; mt < 2; mt++) {
        int row = m0 + wm + mt * 16 + grp;
#pragma unroll
        for (int nt = 0; nt < NT; nt++) {
            int col = n0 + wn + nt * 8 + 2 * t4;
            if (row < N_NODES) {
                float2 v01 = make_float2(acc[mt][nt][0], acc[mt][nt][1]);
                *reinterpret_cast<float2*>(&g_h[(long long)row * BN + col]) = v01;
            }
            if (row + 8 < N_NODES) {
                float2 v23 = make_float2(acc[mt][nt][2], acc[mt][nt][3]);
                *reinterpret_cast<float2*>(&g_h[(long long)(row + 8) * BN + col]) = v23;
            }
        }
    }
}

// ---------------- CSR gather: agg[i] = bias + dis²·h[i] + Σ w·h[src] -------
template <int F, bool EXT_OUT, bool FINAL>
__global__ __launch_bounds__(256)
void k_gather(const float* __restrict__ bias, float* __restrict__ out_ext,
              const float* __restrict__ Wl, const float* __restrict__ bl,
              float* __restrict__ out01) {
    const int NPB = 256 / F;
    __shared__ float red[8];

    int node = blockIdx.x * NPB + threadIdx.x / F;
    int f    = threadIdx.x & (F - 1);
    if (node >= N_NODES) return;

    float dis = g_dis[node];
    float acc = g_h[(long long)node * F + f] * dis * dis + bias[f];

    int beg = g_rowptr[node];
    int end = g_rowptr[node + 1];
    int j = beg;
    for (; j + 4 <= end; j += 4) {
        int   s0 = g_csr_src[j],     s1 = g_csr_src[j + 1];
        int   s2 = g_csr_src[j + 2], s3 = g_csr_src[j + 3];
        float w0 = g_csr_w[j],       w1 = g_csr_w[j + 1];
        float w2 = g_csr_w[j + 2],   w3 = g_csr_w[j + 3];
        float h0 = g_h[(long long)s0 * F + f];
        float h1 = g_h[(long long)s1 * F + f];
        float h2 = g_h[(long long)s2 * F + f];
        float h3 = g_h[(long long)s3 * F + f];
        acc += w0 * h0 + w1 * h1 + w2 * h2 + w3 * h3;
    }
    for (; j < end; j++) {
        int s = g_csr_src[j];
        acc += g_csr_w[j] * g_h[(long long)s * F + f];
    }

    float* o = EXT_OUT ? out_ext : g_agg;
    o[(long long)node * F + f] = acc;

    if (FINAL) {
        float p = acc * Wl[f];
#pragma unroll
        for (int off = 16; off > 0; off >>= 1)
            p += __shfl_down_sync(0xFFFFFFFFu, p, off);
        int warp = threadIdx.x >> 5;
        if ((threadIdx.x & 31) == 0) red[warp] = p;
        __syncthreads();
        if (f == 0) {
            float s = red[warp] + red[warp + 1] + bl[0];
            out01[node] = 1.0f / (1.0f + expf(-s));
        }
    }
}

// ---------------- launcher ---------------------------------------------------
extern "C" void kernel_launch(void* const* d_in, const int* in_sizes, int n_in,
                              void* d_out, int out_size) {
    const float* x    = (const float*)d_in[0];
    const int*   ei32 = (const int*)d_in[1];
    const float* W1 = (const float*)d_in[2];
    const float* b1 = (const float*)d_in[3];
    const float* W2 = (const float*)d_in[4];
    const float* b2 = (const float*)d_in[5];
    const float* W3 = (const float*)d_in[6];
    const float* b3 = (const float*)d_in[7];
    const float* Wl = (const float*)d_in[8];
    const float* bl = (const float*)d_in[9];

    float* out = (float*)d_out;          // [N] sigmoid output first
    float* x3  = out + N_NODES;          // [N, 64] second output region

    const int T = 256;
    dim3 blk(T);
    const int NBn = (N_NODES + T - 1) / T;
    const int NBe = (N_EDGES + T - 1) / T;
    dim3 grid1(F1 / 128, (N_NODES + 127) / 128);   // GEMM1: (2, 391)

    if (g_hx.ok) {
        // fork: CSR build on side stream, GEMM1 on main stream (independent)
        cudaEventRecord(g_hx.e1, 0);
        cudaStreamWaitEvent(g_hx.s2, g_hx.e1, 0);

        k_init<<<NBn, blk, 0, g_hx.s2>>>(ei32);        // 1
        k_deg_count<<<NBe, blk, 0, g_hx.s2>>>(ei32);   // 2
        k_rsqrt<<<NBn, blk, 0, g_hx.s2>>>();           // 3
        k_scan1<<<SCAN_NB, blk, 0, g_hx.s2>>>();       // 4
        k_scan2<<<1, blk, 0, g_hx.s2>>>();             // 5

        k_gemm1_bf16<<<grid1, blk>>>(x, W1);           // 6 (main stream)

        k_scan3<<<SCAN_NB, blk, 0, g_hx.s2>>>();       // 7
        k_fill<<<NBe, blk, 0, g_hx.s2>>>(ei32);        // 8

        // join: gather1 needs both GEMM1 (main) and fill (s2)
        cudaEventRecord(g_hx.e2, g_hx.s2);
        cudaStreamWaitEvent(0, g_hx.e2, 0);
    } else {
        // sequential fallback (deterministic: g_hx.ok is process-constant)
        k_init<<<NBn, blk>>>(ei32);
        k_deg_count<<<NBe, blk>>>(ei32);
        k_rsqrt<<<NBn, blk>>>();
        k_scan1<<<SCAN_NB, blk>>>();
        k_scan2<<<1, blk>>>();
        k_gemm1_bf16<<<grid1, blk>>>(x, W1);
        k_scan3<<<SCAN_NB, blk>>>();
        k_fill<<<NBe, blk>>>(ei32);
    }

    // ---- layer 1 aggregation ----
    k_gather<F1, false, false><<<N_NODES / (256 / F1), blk>>>(
        b1, nullptr, nullptr, nullptr, nullptr);

    // ---- layer 2: 256 -> 128 (tf32 MMA, ReLU fused into A-load) ----
    {
        dim3 grid((N_NODES + 127) / 128, 1);
        k_gemm23<F1, F2, true><<<grid, blk>>>(W2);
        k_gather<F2, false, false><<<N_NODES / (256 / F2), blk>>>(
            b2, nullptr, nullptr, nullptr, nullptr);
    }

    // ---- layer 3: 128 -> 64 (tf32 MMA); gather writes x3 + fused head ----
    {
        dim3 grid((N_NODES + 127) / 128, 1);
        k_gemm23<F2, F3, false><<<grid, blk>>>(W3);
        k_gather<F3, true, true><<<N_NODES / (256 / F3), blk>>>(
            b3, x3, Wl, bl, out);
    }
}

// round 10
// speedup vs baseline: 5.1254x; 1.1393x over previous
#include <cuda_runtime.h>
#include <cstdint>

#define N_NODES 50000
#define N_EDGES 1600000
#define D_IN    3000
#define F1      256
#define F2      128
#define F3      64
#define SCAN_NB ((N_NODES + 255) / 256)   // 196

// ---------------- scratch (static device arrays; alloc-free rule) ----------
__device__ float    g_h[(size_t)N_NODES * F1];        // fp32 h (layer 3)
__device__ uint32_t g_hb[(size_t)N_NODES * (F1 / 2)]; // bf16x2 h (layers 1,2)
__device__ float    g_agg[(size_t)N_NODES * F1];
__device__ float    g_dis[N_NODES];
__device__ int      g_indeg[N_NODES];
__device__ int      g_rowptr[N_NODES + 1];
__device__ int      g_cursor[N_NODES];
__device__ int      g_csr_src[N_EDGES];
__device__ float    g_csr_w[N_EDGES];
__device__ int      g_blocksum[256];
__device__ int      g_is64;

// ---------------- host-side streams (created at program init, pre-capture) --
namespace {
struct HxStreams {
    cudaStream_t s2 = nullptr;
    cudaEvent_t  e1 = nullptr, e2 = nullptr;
    bool ok = false;
    HxStreams() {
        ok = (cudaStreamCreateWithFlags(&s2, cudaStreamNonBlocking) == cudaSuccess) &&
             (cudaEventCreateWithFlags(&e1, cudaEventDisableTiming) == cudaSuccess) &&
             (cudaEventCreateWithFlags(&e2, cudaEventDisableTiming) == cudaSuccess);
    }
};
HxStreams g_hx;
}

// ---------------- init: zero counters + dtype probe (block 0) ---------------
__global__ void k_init(const int* __restrict__ ei32) {
    int i = blockIdx.x * blockDim.x + threadIdx.x;
    if (i < N_NODES) { g_indeg[i] = 0; g_cursor[i] = 0; }
    if (blockIdx.x == 0) {
        __shared__ int bad;
        if (threadIdx.x == 0) bad = 0;
        __syncthreads();
        for (int j = threadIdx.x; j < 2048; j += blockDim.x)
            if (ei32[2 * j + 1] != 0) atomicOr(&bad, 1);
        __syncthreads();
        if (threadIdx.x == 0) g_is64 = bad ? 0 : 1;
    }
}

__device__ __forceinline__ int load_idx(const int* __restrict__ ei32, long long pos) {
    int v = g_is64 ? ei32[2 * pos] : ei32[pos];
    v = v < 0 ? 0 : (v >= N_NODES ? N_NODES - 1 : v);
    return v;
}

// ---------------- degree / CSR build ----------------------------------------
__global__ void k_deg_count(const int* __restrict__ ei32) {
    int e = blockIdx.x * blockDim.x + threadIdx.x;
    if (e < N_EDGES) {
        int d = load_idx(ei32, (long long)N_EDGES + e);
        atomicAdd(&g_indeg[d], 1);
    }
}

__global__ void k_rsqrt() {
    int i = blockIdx.x * blockDim.x + threadIdx.x;
    if (i < N_NODES) g_dis[i] = rsqrtf((float)g_indeg[i] + 1.0f);
}

__global__ void k_scan1() {
    __shared__ int s[256];
    int b = blockIdx.x, t = threadIdx.x;
    int i = b * 256 + t;
    int v = (i < N_NODES) ? g_indeg[i] : 0;
    s[t] = v;
    __syncthreads();
#pragma unroll
    for (int off = 1; off < 256; off <<= 1) {
        int add = (t >= off) ? s[t - off] : 0;
        __syncthreads();
        s[t] += add;
        __syncthreads();
    }
    if (i < N_NODES) g_rowptr[i + 1] = s[t];
    if (t == 255) g_blocksum[b] = s[255];
}

__global__ void k_scan2() {
    __shared__ int s[256];
    int t = threadIdx.x;
    int v = (t < SCAN_NB) ? g_blocksum[t] : 0;
    s[t] = v;
    __syncthreads();
#pragma unroll
    for (int off = 1; off < 256; off <<= 1) {
        int add = (t >= off) ? s[t - off] : 0;
        __syncthreads();
        s[t] += add;
        __syncthreads();
    }
    g_blocksum[t] = s[t] - v;
}

__global__ void k_scan3() {
    int i = blockIdx.x * blockDim.x + threadIdx.x;
    if (i < N_NODES) g_rowptr[i + 1] += g_blocksum[blockIdx.x];
    if (i == 0) g_rowptr[0] = 0;
}

__global__ void k_fill(const int* __restrict__ ei32) {
    int e = blockIdx.x * blockDim.x + threadIdx.x;
    if (e < N_EDGES) {
        int s = load_idx(ei32, e);
        int d = load_idx(ei32, (long long)N_EDGES + e);
        int pos = g_rowptr[d] + atomicAdd(&g_cursor[d], 1);
        g_csr_src[pos] = s;
        g_csr_w[pos]   = g_dis[s] * g_dis[d];
    }
}

// ---------------- format helpers ---------------------------------------------
__device__ __forceinline__ uint32_t f2tf32(float x) {
    uint32_t r;
    asm("cvt.rna.tf32.f32 %0, %1;" : "=r"(r) : "f"(x));
    return r;
}

__device__ __forceinline__ uint32_t pack_bf16(float lo, float hi) {
    uint32_t r;
    asm("cvt.rn.bf16x2.f32 %0, %1, %2;" : "=r"(r) : "f"(hi), "f"(lo));
    return r;
}

__device__ __forceinline__ float bf_lo(uint32_t u) { return __uint_as_float(u << 16); }
__device__ __forceinline__ float bf_hi(uint32_t u) { return __uint_as_float(u & 0xFFFF0000u); }

__device__ __forceinline__ void mma_tf32(float& c0, float& c1, float& c2, float& c3,
                                         uint32_t a0, uint32_t a1, uint32_t a2, uint32_t a3,
                                         uint32_t b0, uint32_t b1) {
    asm volatile(
        "mma.sync.aligned.m16n8k8.row.col.f32.tf32.tf32.f32 "
        "{%0,%1,%2,%3}, {%4,%5,%6,%7}, {%8,%9}, {%0,%1,%2,%3};"
        : "+f"(c0), "+f"(c1), "+f"(c2), "+f"(c3)
        : "r"(a0), "r"(a1), "r"(a2), "r"(a3), "r"(b0), "r"(b1));
}

__device__ __forceinline__ void mma_bf16(float& c0, float& c1, float& c2, float& c3,
                                         uint32_t a0, uint32_t a1, uint32_t a2, uint32_t a3,
                                         uint32_t b0, uint32_t b1) {
    asm volatile(
        "mma.sync.aligned.m16n8k16.row.col.f32.bf16.bf16.f32 "
        "{%0,%1,%2,%3}, {%4,%5,%6,%7}, {%8,%9}, {%0,%1,%2,%3};"
        : "+f"(c0), "+f"(c1), "+f"(c2), "+f"(c3)
        : "r"(a0), "r"(a1), "r"(a2), "r"(a3), "r"(b0), "r"(b1));
}

// ---------------- GEMM1: g_hb[M,256/2] = bf16(x @ W1) (bf16 MMA) ------------
__global__ __launch_bounds__(256)
void k_gemm1_bf16(const float* __restrict__ A, const float* __restrict__ B) {
    const int BM = 128, LDS_S = 132;
    __shared__ uint32_t As32[2][8][LDS_S];
    __shared__ uint32_t Bs32[2][8][LDS_S];

    const int tid  = threadIdx.x;
    const int m0   = blockIdx.y * BM;
    const int n0   = blockIdx.x * 128;
    const int warp = tid >> 5, lane = tid & 31;
    const int wm = (warp & 3) * 32;
    const int wn = (warp >> 2) * 64;
    const int grp = lane >> 2, t4 = lane & 3;

    float acc[2][8][4];
#pragma unroll
    for (int i = 0; i < 2; i++)
#pragma unroll
        for (int j = 0; j < 8; j++)
#pragma unroll
            for (int q = 0; q < 4; q++) acc[i][j][q] = 0.0f;

    int arow[2], akc[2];
    const float* aptr[2];
    bool aval[2];
#pragma unroll
    for (int i = 0; i < 2; i++) {
        int f = tid + i * 256;
        arow[i] = f >> 2;
        akc[i]  = (f & 3) * 4;
        int gm  = m0 + arow[i];
        aval[i] = (gm < N_NODES);
        aptr[i] = A + (long long)(aval[i] ? gm : 0) * D_IN;
    }
    const int bkk = tid >> 5;
    const int bn  = (tid & 31) * 4;

    const int NK = (D_IN + 15) / 16;   // 188

    float4 ra[2], rb0, rb1;
    auto load_tiles = [&](int k0) {
#pragma unroll
        for (int i = 0; i < 2; i++) {
            ra[i] = make_float4(0.f, 0.f, 0.f, 0.f);
            if (aval[i] && (k0 + akc[i] < D_IN))
                ra[i] = *reinterpret_cast<const float4*>(aptr[i] + k0 + akc[i]);
        }
        rb0 = make_float4(0.f, 0.f, 0.f, 0.f);
        rb1 = make_float4(0.f, 0.f, 0.f, 0.f);
        int kr = k0 + 2 * bkk;
        if (kr < D_IN) {
            rb0 = *reinterpret_cast<const float4*>(&B[(long long)kr * F1 + n0 + bn]);
            rb1 = *reinterpret_cast<const float4*>(&B[(long long)(kr + 1) * F1 + n0 + bn]);
        }
    };
    auto store_tiles = [&](int buf) {
#pragma unroll
        for (int i = 0; i < 2; i++) {
            int kk = akc[i] >> 1;
            As32[buf][kk + 0][arow[i]] = pack_bf16(ra[i].x, ra[i].y);
            As32[buf][kk + 1][arow[i]] = pack_bf16(ra[i].z, ra[i].w);
        }
        uint4 u;
        u.x = pack_bf16(rb0.x, rb1.x);
        u.y = pack_bf16(rb0.y, rb1.y);
        u.z = pack_bf16(rb0.z, rb1.z);
        u.w = pack_bf16(rb0.w, rb1.w);
        *reinterpret_cast<uint4*>(&Bs32[buf][bkk][bn]) = u;
    };

    load_tiles(0);
    store_tiles(0);
    __syncthreads();

    for (int it = 0; it < NK; it++) {
        int buf = it & 1;
        if (it + 1 < NK) load_tiles((it + 1) * 16);

        uint32_t af[2][4], bf[8][2];
#pragma unroll
        for (int mt = 0; mt < 2; mt++) {
            int r = wm + mt * 16 + grp;
            af[mt][0] = As32[buf][t4][r];
            af[mt][1] = As32[buf][t4][r + 8];
            af[mt][2] = As32[buf][t4 + 4][r];
            af[mt][3] = As32[buf][t4 + 4][r + 8];
        }
#pragma unroll
        for (int nt = 0; nt < 8; nt++) {
            int c = wn + nt * 8 + grp;
            bf[nt][0] = Bs32[buf][t4][c];
            bf[nt][1] = Bs32[buf][t4 + 4][c];
        }
#pragma unroll
        for (int mt = 0; mt < 2; mt++)
#pragma unroll
            for (int nt = 0; nt < 8; nt++)
                mma_bf16(acc[mt][nt][0], acc[mt][nt][1],
                         acc[mt][nt][2], acc[mt][nt][3],
                         af[mt][0], af[mt][1], af[mt][2], af[mt][3],
                         bf[nt][0], bf[nt][1]);

        if (it + 1 < NK) store_tiles(buf ^ 1);
        __syncthreads();
    }

    // store as bf16x2: (c0,c1) are adjacent columns -> one u32
#pragma unroll
    for (int mt = 0; mt < 2; mt++) {
        int row = m0 + wm + mt * 16 + grp;
#pragma unroll
        for (int nt = 0; nt < 8; nt++) {
            int col = n0 + wn + nt * 8 + 2 * t4;   // even
            if (row < N_NODES)
                g_hb[(size_t)row * (F1 / 2) + (col >> 1)] =
                    pack_bf16(acc[mt][nt][0], acc[mt][nt][1]);
            if (row + 8 < N_NODES)
                g_hb[(size_t)(row + 8) * (F1 / 2) + (col >> 1)] =
                    pack_bf16(acc[mt][nt][2], acc[mt][nt][3]);
        }
    }
}

// ---------------- GEMM 2/3: op(g_agg)[M,KD] @ B[KD,BN] (tf32) ---------------
// HB_OUT: store bf16x2 to g_hb (layer 2); else fp32 to g_h (layer 3).
template <int KD, int BN, bool RELU_A, bool HB_OUT>
__global__ __launch_bounds__(256)
void k_gemm23(const float* __restrict__ B) {
    const int NT = BN / 16;
    __shared__ uint32_t As[16][132];
    __shared__ uint32_t Bs[16][BN + 4];

    const int tid  = threadIdx.x;
    const int m0   = blockIdx.x * 128;
    const int n0   = blockIdx.y * BN;
    const int warp = tid >> 5, lane = tid & 31;
    const int wm = (warp & 3) * 32;
    const int wn = (warp >> 2) * (BN / 2);
    const int grp = lane >> 2, t4 = lane & 3;

    float acc[2][NT][4];
#pragma unroll
    for (int i = 0; i < 2; i++)
#pragma unroll
        for (int j = 0; j < NT; j++)
#pragma unroll
            for (int q = 0; q < 4; q++) acc[i][j][q] = 0.0f;

    int arow[2], akc[2];
#pragma unroll
    for (int i = 0; i < 2; i++) {
        int f = tid + i * 256;
        arow[i] = f >> 2;
        akc[i]  = (f & 3) * 4;
    }

    for (int k0 = 0; k0 < KD; k0 += 16) {
#pragma unroll
        for (int i = 0; i < 2; i++) {
            int gm = m0 + arow[i];
            float4 v = make_float4(0.f, 0.f, 0.f, 0.f);
            if (gm < N_NODES)
                v = *reinterpret_cast<const float4*>(
                        &g_agg[(long long)gm * KD + k0 + akc[i]]);
            if (RELU_A) {
                v.x = fmaxf(v.x, 0.f); v.y = fmaxf(v.y, 0.f);
                v.z = fmaxf(v.z, 0.f); v.w = fmaxf(v.w, 0.f);
            }
            As[akc[i] + 0][arow[i]] = f2tf32(v.x);
            As[akc[i] + 1][arow[i]] = f2tf32(v.y);
            As[akc[i] + 2][arow[i]] = f2tf32(v.z);
            As[akc[i] + 3][arow[i]] = f2tf32(v.w);
        }
        {
            const int NF = 4 * BN;
#pragma unroll
            for (int i = 0; i < NF / 256; i++) {
                int f = tid + i * 256;
                int br = f / (BN / 4);
                int bc = (f % (BN / 4)) * 4;
                float4 v = *reinterpret_cast<const float4*>(
                    &B[(long long)(k0 + br) * BN + n0 + bc]);
                Bs[br][bc + 0] = f2tf32(v.x);
                Bs[br][bc + 1] = f2tf32(v.y);
                Bs[br][bc + 2] = f2tf32(v.z);
                Bs[br][bc + 3] = f2tf32(v.w);
            }
        }
        __syncthreads();

#pragma unroll
        for (int kb = 0; kb < 16; kb += 8) {
            uint32_t af[2][4], bfr[NT][2];
#pragma unroll
            for (int mt = 0; mt < 2; mt++) {
                int r = wm + mt * 16 + grp;
                af[mt][0] = As[kb + t4][r];
                af[mt][1] = As[kb + t4][r + 8];
                af[mt][2] = As[kb + t4 + 4][r];
                af[mt][3] = As[kb + t4 + 4][r + 8];
            }
#pragma unroll
            for (int nt = 0; nt < NT; nt++) {
                int c = wn + nt * 8 + grp;
                bfr[nt][0] = Bs[kb + t4][c];
                bfr[nt][1] = Bs[kb + t4 + 4][c];
            }
#pragma unroll
            for (int mt = 0; mt < 2; mt++)
#pragma unroll
                for (int nt = 0; nt < NT; nt++)
                    mma_tf32(acc[mt][nt][0], acc[mt][nt][1],
                             acc[mt][nt][2], acc[mt][nt][3],
                             af[mt][0], af[mt][1], af[mt][2], af[mt][3],
                             bfr[nt][0], bfr[nt][1]);
        }
        __syncthreads();
    }

#pragma unroll
    for (int mt = 0; mt < 2; mt++) {
        int row = m0 + wm + mt * 16 + grp;
#pragma unroll
        for (int nt = 0; nt < NT; nt++) {
            int col = n0 + wn + nt * 8 + 2 * t4;
            if (HB_OUT) {
                if (row < N_NODES)
                    g_hb[(size_t)row * (BN / 2) + (col >> 1)] =
                        pack_bf16(acc[mt][nt][0], acc[mt][nt][1]);
                if (row + 8 < N_NODES)
                    g_hb[(size_t)(row + 8) * (BN / 2) + (col >> 1)] =
                        pack_bf16(acc[mt][nt][2], acc[mt][nt][3]);
            } else {
                if (row < N_NODES) {
                    float2 v01 = make_float2(acc[mt][nt][0], acc[mt][nt][1]);
                    *reinterpret_cast<float2*>(&g_h[(long long)row * BN + col]) = v01;
                }
                if (row + 8 < N_NODES) {
                    float2 v23 = make_float2(acc[mt][nt][2], acc[mt][nt][3]);
                    *reinterpret_cast<float2*>(&g_h[(long long)(row + 8) * BN + col]) = v23;
                }
            }
        }
    }
}

// ---------------- CSR gather (bf16 h): agg = bias + dis²·h + Σ w·h[src] ----
// h stored as bf16x2; each thread owns one u32 (2 features) of one node.
template <int F>
__global__ __launch_bounds__(256)
void k_gather_hb(const float* __restrict__ bias) {
    const int C = F / 2;              // u32 per node
    const int NPB = 256 / C;

    int node = blockIdx.x * NPB + threadIdx.x / C;
    int c    = threadIdx.x & (C - 1);

    float dis = g_dis[node];
    float d2  = dis * dis;
    uint32_t hp = g_hb[(size_t)node * C + c];
    float ax = bf_lo(hp) * d2 + bias[2 * c];
    float ay = bf_hi(hp) * d2 + bias[2 * c + 1];

    int beg = g_rowptr[node];
    int end = g_rowptr[node + 1];
    int j = beg;
    for (; j + 4 <= end; j += 4) {
        int   s0 = g_csr_src[j],     s1 = g_csr_src[j + 1];
        int   s2 = g_csr_src[j + 2], s3 = g_csr_src[j + 3];
        float w0 = g_csr_w[j],       w1 = g_csr_w[j + 1];
        float w2 = g_csr_w[j + 2],   w3 = g_csr_w[j + 3];
        uint32_t p0 = g_hb[(size_t)s0 * C + c];
        uint32_t p1 = g_hb[(size_t)s1 * C + c];
        uint32_t p2 = g_hb[(size_t)s2 * C + c];
        uint32_t p3 = g_hb[(size_t)s3 * C + c];
        ax += w0 * bf_lo(p0) + w1 * bf_lo(p1) + w2 * bf_lo(p2) + w3 * bf_lo(p3);
        ay += w0 * bf_hi(p0) + w1 * bf_hi(p1) + w2 * bf_hi(p2) + w3 * bf_hi(p3);
    }
    for (; j < end; j++) {
        int s = g_csr_src[j];
        float w = g_csr_w[j];
        uint32_t p = g_hb[(size_t)s * C + c];
        ax += w * bf_lo(p);
        ay += w * bf_hi(p);
    }

    *reinterpret_cast<float2*>(&g_agg[(size_t)node * F + 2 * c]) =
        make_float2(ax, ay);
}

// ---------------- CSR gather (fp32 h, layer 3 + fused head) -----------------
template <int F>
__global__ __launch_bounds__(256)
void k_gather_final(const float* __restrict__ bias, float* __restrict__ out_ext,
                    const float* __restrict__ Wl, const float* __restrict__ bl,
                    float* __restrict__ out01) {
    const int NPB = 256 / F;
    __shared__ float red[8];

    int node = blockIdx.x * NPB + threadIdx.x / F;
    int f    = threadIdx.x & (F - 1);

    float dis = g_dis[node];
    float acc = g_h[(long long)node * F + f] * dis * dis + bias[f];

    int beg = g_rowptr[node];
    int end = g_rowptr[node + 1];
    int j = beg;
    for (; j + 4 <= end; j += 4) {
        int   s0 = g_csr_src[j],     s1 = g_csr_src[j + 1];
        int   s2 = g_csr_src[j + 2], s3 = g_csr_src[j + 3];
        float w0 = g_csr_w[j],       w1 = g_csr_w[j + 1];
        float w2 = g_csr_w[j + 2],   w3 = g_csr_w[j + 3];
        acc += w0 * g_h[(long long)s0 * F + f] + w1 * g_h[(long long)s1 * F + f]
             + w2 * g_h[(long long)s2 * F + f] + w3 * g_h[(long long)s3 * F + f];
    }
    for (; j < end; j++)
        acc += g_csr_w[j] * g_h[(long long)g_csr_src[j] * F + f];

    out_ext[(long long)node * F + f] = acc;

    float p = acc * Wl[f];
#pragma unroll
    for (int off = 16; off > 0; off >>= 1)
        p += __shfl_down_sync(0xFFFFFFFFu, p, off);
    int warp = threadIdx.x >> 5;
    if ((threadIdx.x & 31) == 0) red[warp] = p;
    __syncthreads();
    if (f == 0) {
        float s = red[warp] + red[warp + 1] + bl[0];
        out01[node] = 1.0f / (1.0f + expf(-s));
    }
}

// ---------------- launcher ---------------------------------------------------
extern "C" void kernel_launch(void* const* d_in, const int* in_sizes, int n_in,
                              void* d_out, int out_size) {
    const float* x    = (const float*)d_in[0];
    const int*   ei32 = (const int*)d_in[1];
    const float* W1 = (const float*)d_in[2];
    const float* b1 = (const float*)d_in[3];
    const float* W2 = (const float*)d_in[4];
    const float* b2 = (const float*)d_in[5];
    const float* W3 = (const float*)d_in[6];
    const float* b3 = (const float*)d_in[7];
    const float* Wl = (const float*)d_in[8];
    const float* bl = (const float*)d_in[9];

    float* out = (float*)d_out;          // [N] sigmoid output first
    float* x3  = out + N_NODES;          // [N, 64] second output region

    const int T = 256;
    dim3 blk(T);
    const int NBn = (N_NODES + T - 1) / T;
    const int NBe = (N_EDGES + T - 1) / T;
    dim3 grid1(F1 / 128, (N_NODES + 127) / 128);

    if (g_hx.ok) {
        cudaEventRecord(g_hx.e1, 0);
        cudaStreamWaitEvent(g_hx.s2, g_hx.e1, 0);

        k_init<<<NBn, blk, 0, g_hx.s2>>>(ei32);
        k_deg_count<<<NBe, blk, 0, g_hx.s2>>>(ei32);
        k_rsqrt<<<NBn, blk, 0, g_hx.s2>>>();
        k_scan1<<<SCAN_NB, blk, 0, g_hx.s2>>>();
        k_scan2<<<1, blk, 0, g_hx.s2>>>();

        k_gemm1_bf16<<<grid1, blk>>>(x, W1);

        k_scan3<<<SCAN_NB, blk, 0, g_hx.s2>>>();
        k_fill<<<NBe, blk, 0, g_hx.s2>>>(ei32);

        cudaEventRecord(g_hx.e2, g_hx.s2);
        cudaStreamWaitEvent(0, g_hx.e2, 0);
    } else {
        k_init<<<NBn, blk>>>(ei32);
        k_deg_count<<<NBe, blk>>>(ei32);
        k_rsqrt<<<NBn, blk>>>();
        k_scan1<<<SCAN_NB, blk>>>();
        k_scan2<<<1, blk>>>();
        k_gemm1_bf16<<<grid1, blk>>>(x, W1);
        k_scan3<<<SCAN_NB, blk>>>();
        k_fill<<<NBe, blk>>>(ei32);
    }

    // ---- layer 1 aggregation (bf16 h) ----
    k_gather_hb<F1><<<N_NODES / (512 / F1), blk>>>(b1);

    // ---- layer 2: 256 -> 128 (tf32 MMA; bf16x2 output) ----
    {
        dim3 grid((N_NODES + 127) / 128, 1);
        k_gemm23<F1, F2, true, true><<<grid, blk>>>(W2);
        k_gather_hb<F2><<<N_NODES / (512 / F2), blk>>>(b2);
    }

    // ---- layer 3: 128 -> 64 (tf32 MMA, fp32 h); gather writes x3 + head ----
    {
        dim3 grid((N_NODES + 127) / 128, 1);
        k_gemm23<F2, F3, false, false><<<grid, blk>>>(W3);
        k_gather_final<F3><<<N_NODES / (256 / F3), blk>>>(b3, x3, Wl, bl, out);
    }
}